// round 6
// baseline (speedup 1.0000x reference)
#include <cuda_runtime.h>
#include <math.h>
#include <stdint.h>

#define B_  8
#define N_  1024
#define D_  256
#define H_  4
#define DH_ 64
#define M_  512
#define EPS_ 1e-5f

// ---------------- scratch (device globals; no allocations allowed) ----------
__device__ float g_h[B_*N_*D_];                 // LN output
__device__ float g_qkv[B_*N_*3*D_];             // qkv
__device__ float g_o[B_*N_*D_];                 // attn out
__device__ float g_y[B_*N_*D_];                 // branch output
__device__ float g_t1[B_*N_*M_];                // fc1/gelu out
__device__ float g_t2[B_*N_*M_];                // conv/bn/gelu out
__device__ float g_mean[B_*D_];
__device__ float g_gate[B_*D_];

__device__ __forceinline__ float gelu_exact(float v) {
    return 0.5f * v * (1.f + erff(v * 0.70710678118654752f));
}

__device__ __forceinline__ void mma_tf32(float& c0, float& c1, float& c2, float& c3,
                                         float a0, float a1, float a2, float a3,
                                         float b0, float b1)
{
    asm volatile(
        "mma.sync.aligned.m16n8k8.row.col.f32.tf32.tf32.f32 "
        "{%0,%1,%2,%3},{%4,%5,%6,%7},{%8,%9},{%0,%1,%2,%3};"
        : "+f"(c0), "+f"(c1), "+f"(c2), "+f"(c3)
        : "r"(__float_as_uint(a0)), "r"(__float_as_uint(a1)),
          "r"(__float_as_uint(a2)), "r"(__float_as_uint(a3)),
          "r"(__float_as_uint(b0)), "r"(__float_as_uint(b1)));
}

__device__ __forceinline__ void cp16(uint32_t dst, const void* src) {
    asm volatile("cp.async.cg.shared.global [%0], [%1], 16;" :: "r"(dst), "l"(src));
}
__device__ __forceinline__ void cp_commit() {
    asm volatile("cp.async.commit_group;" ::: "memory");
}
__device__ __forceinline__ void cp_wait0() {
    asm volatile("cp.async.wait_group 0;" ::: "memory");
}
__device__ __forceinline__ uint32_t smem_u32(const void* p) {
    return (uint32_t)__cvta_generic_to_shared(p);
}

// ---------------- flash attention --------------------------------------------
// One CTA = 128 query rows of one (b,h). 8 warps x 16 rows. Iterates 16 KV
// tiles of 64, K/V double-buffered via cp.async. Online softmax in registers.
#define FBM 128
#define FBN 64
#define FWARPS 8

struct FlashSmem {
    float Q[FBM][68];           // q rows (pre-scaled), m-major
    float K[2][FBN][68];        // kv-major [kv][d]
    float V[2][FBN][72];        // k-major  [kv][d]
    float P[FWARPS][16][68];    // per-warp probs staging
};
#define FLASH_SMEM_BYTES ((int)sizeof(FlashSmem))

__global__ __launch_bounds__(FWARPS*32)
void flash_k(const float* __restrict__ qkv, float* __restrict__ Og)
{
    extern __shared__ float smem_raw[];
    FlashSmem& S = *(FlashSmem*)smem_raw;

    const int bh = blockIdx.z;
    const int b = bh >> 2, h = bh & 3;
    const int m0 = blockIdx.y * FBM;
    const int tid  = threadIdx.x;
    const int warp = tid >> 5, lane = tid & 31;
    const int gid  = lane >> 2, tig = lane & 3;
    const int NT = FWARPS * 32;

    const float* qb = qkv + ((size_t)b * N_) * (3*D_) + h * DH_;

    // load Q tile once, scaled by DH^-0.5
    #pragma unroll
    for (int i = 0; i < FBM * 16 / NT; i++) {
        int v = tid + i * NT;
        int r = v >> 4, dq = v & 15;
        float4 t = *(const float4*)&qb[(size_t)(m0 + r) * (3*D_) + dq * 4];
        t.x *= 0.125f; t.y *= 0.125f; t.z *= 0.125f; t.w *= 0.125f;
        *(float4*)&S.Q[r][dq * 4] = t;
    }

    auto issue = [&](int buf, int t) {
        int n0 = t * FBN;
        const float* kb = qkv + ((size_t)b * N_ + n0) * (3*D_) + D_ + h * DH_;
        const float* vb = kb + D_;
        #pragma unroll
        for (int i = 0; i < FBN * 16 / NT; i++) {
            int v = tid + i * NT;
            int r = v >> 4, dq = v & 15;
            cp16(smem_u32(&S.K[buf][r][dq * 4]), &kb[(size_t)r * (3*D_) + dq * 4]);
            cp16(smem_u32(&S.V[buf][r][dq * 4]), &vb[(size_t)r * (3*D_) + dq * 4]);
        }
    };

    float mr0 = -1e30f, mr1 = -1e30f, l0 = 0.f, l1 = 0.f;
    float o[8][4];
    #pragma unroll
    for (int nt = 0; nt < 8; nt++)
        #pragma unroll
        for (int c = 0; c < 4; c++) o[nt][c] = 0.f;

    const int qrow = warp * 16 + gid;

    issue(0, 0); cp_commit();
    for (int t = 0; t < N_ / FBN; t++) {
        int cur = t & 1;
        cp_wait0();
        __syncthreads();             // tile t visible; all warps done with t-1
        if (t + 1 < N_ / FBN) { issue(cur ^ 1, t + 1); cp_commit(); }

        // ---- S = Qs @ K^T ----
        float s[8][4];
        #pragma unroll
        for (int nt = 0; nt < 8; nt++)
            #pragma unroll
            for (int c = 0; c < 4; c++) s[nt][c] = 0.f;

        #pragma unroll
        for (int ks = 0; ks < DH_; ks += 8) {
            float a0 = S.Q[qrow    ][ks + tig];
            float a1 = S.Q[qrow + 8][ks + tig];
            float a2 = S.Q[qrow    ][ks + tig + 4];
            float a3 = S.Q[qrow + 8][ks + tig + 4];
            #pragma unroll
            for (int nt = 0; nt < 8; nt++) {
                float b0 = S.K[cur][nt * 8 + gid][ks + tig];
                float b1 = S.K[cur][nt * 8 + gid][ks + tig + 4];
                mma_tf32(s[nt][0], s[nt][1], s[nt][2], s[nt][3],
                         a0, a1, a2, a3, b0, b1);
            }
        }

        // ---- online softmax update ----
        float rm0 = -1e30f, rm1 = -1e30f;
        #pragma unroll
        for (int nt = 0; nt < 8; nt++) {
            rm0 = fmaxf(rm0, fmaxf(s[nt][0], s[nt][1]));
            rm1 = fmaxf(rm1, fmaxf(s[nt][2], s[nt][3]));
        }
        rm0 = fmaxf(rm0, __shfl_xor_sync(0xffffffff, rm0, 1));
        rm0 = fmaxf(rm0, __shfl_xor_sync(0xffffffff, rm0, 2));
        rm1 = fmaxf(rm1, __shfl_xor_sync(0xffffffff, rm1, 1));
        rm1 = fmaxf(rm1, __shfl_xor_sync(0xffffffff, rm1, 2));

        float mn0 = fmaxf(mr0, rm0), mn1 = fmaxf(mr1, rm1);
        float sc0 = __expf(mr0 - mn0), sc1 = __expf(mr1 - mn1);
        mr0 = mn0; mr1 = mn1;

        float rs0 = 0.f, rs1 = 0.f;
        #pragma unroll
        for (int nt = 0; nt < 8; nt++) {
            s[nt][0] = __expf(s[nt][0] - mn0);
            s[nt][1] = __expf(s[nt][1] - mn0);
            s[nt][2] = __expf(s[nt][2] - mn1);
            s[nt][3] = __expf(s[nt][3] - mn1);
            rs0 += s[nt][0] + s[nt][1];
            rs1 += s[nt][2] + s[nt][3];
        }
        rs0 += __shfl_xor_sync(0xffffffff, rs0, 1);
        rs0 += __shfl_xor_sync(0xffffffff, rs0, 2);
        rs1 += __shfl_xor_sync(0xffffffff, rs1, 1);
        rs1 += __shfl_xor_sync(0xffffffff, rs1, 2);
        l0 = l0 * sc0 + rs0;
        l1 = l1 * sc1 + rs1;

        #pragma unroll
        for (int nt = 0; nt < 8; nt++) {
            o[nt][0] *= sc0; o[nt][1] *= sc0;
            o[nt][2] *= sc1; o[nt][3] *= sc1;
        }

        // ---- stage P in warp-private smem ----
        #pragma unroll
        for (int nt = 0; nt < 8; nt++) {
            S.P[warp][gid    ][nt * 8 + tig * 2    ] = s[nt][0];
            S.P[warp][gid    ][nt * 8 + tig * 2 + 1] = s[nt][1];
            S.P[warp][gid + 8][nt * 8 + tig * 2    ] = s[nt][2];
            S.P[warp][gid + 8][nt * 8 + tig * 2 + 1] = s[nt][3];
        }
        __syncwarp();

        // ---- O += P @ V ----
        #pragma unroll
        for (int ks = 0; ks < FBN; ks += 8) {
            float a0 = S.P[warp][gid    ][ks + tig];
            float a1 = S.P[warp][gid + 8][ks + tig];
            float a2 = S.P[warp][gid    ][ks + tig + 4];
            float a3 = S.P[warp][gid + 8][ks + tig + 4];
            #pragma unroll
            for (int nt = 0; nt < 8; nt++) {
                float b0 = S.V[cur][ks + tig    ][nt * 8 + gid];
                float b1 = S.V[cur][ks + tig + 4][nt * 8 + gid];
                mma_tf32(o[nt][0], o[nt][1], o[nt][2], o[nt][3],
                         a0, a1, a2, a3, b0, b1);
            }
        }
        __syncwarp();
    }

    // ---- epilogue ----
    float inv0 = 1.f / l0, inv1 = 1.f / l1;
    int r0 = m0 + qrow;
    float* ob0 = Og + ((size_t)b * N_ + r0    ) * D_ + h * DH_;
    float* ob1 = Og + ((size_t)b * N_ + r0 + 8) * D_ + h * DH_;
    #pragma unroll
    for (int nt = 0; nt < 8; nt++) {
        int col = nt * 8 + tig * 2;
        *(float2*)&ob0[col] = make_float2(o[nt][0] * inv0, o[nt][1] * inv0);
        *(float2*)&ob1[col] = make_float2(o[nt][2] * inv1, o[nt][3] * inv1);
    }
}

// ---------------- batched tensor-core GEMM v4 (tf32, cp.async) ---------------
// 128 threads = 4 warps in 2x2; warp tile (BM/2)x(BN/2).
template<int BM, int BN, bool TRANSB, int ACT>
__global__ __launch_bounds__(128)
void gemm4_k(const float* __restrict__ A, int lda, long sAo, long sAi,
             const float* __restrict__ Bm, int ldb, long sBo, long sBi,
             float* __restrict__ C, int ldc, long sCo, long sCi,
             const float* __restrict__ bias, int K, int Hdiv, float alpha)
{
    constexpr int BK = 16;
    constexpr int NT = 128;
    constexpr int WM = BM / 2, WN = BN / 2;
    constexpr int MT = WM / 16, NTL = WN / 8;
    constexpr int SA = BK + 4;
    constexpr int LA = BM * BK / (4 * NT);
    constexpr int LB = BN * BK / (4 * NT);
    constexpr int BSR = TRANSB ? BN : BK;
    constexpr int BSC = TRANSB ? SA : BN + 8;

    __shared__ __align__(16) float As[2][BM][SA];
    __shared__ __align__(16) float Bs[2][BSR][BSC];

    int z  = blockIdx.z;
    int bb = z / Hdiv, hh = z % Hdiv;
    A  += (size_t)bb * sAo + (size_t)hh * sAi;
    Bm += (size_t)bb * sBo + (size_t)hh * sBi;
    C  += (size_t)bb * sCo + (size_t)hh * sCi;

    const int m0 = blockIdx.y * BM;
    const int n0 = blockIdx.x * BN;
    const int tid   = threadIdx.x;
    const int warp  = tid >> 5;
    const int lane  = tid & 31;
    const int gid   = lane >> 2;
    const int tig   = lane & 3;
    const int warpM = warp >> 1;
    const int warpN = warp & 1;

    auto issue = [&](int buf, int k0) {
        #pragma unroll
        for (int i = 0; i < LA; i++) {
            int v = tid + i * NT;
            int m = v >> 2, kq = v & 3;
            cp16(smem_u32(&As[buf][m][kq * 4]),
                 &A[(size_t)(m0 + m) * lda + k0 + kq * 4]);
        }
        #pragma unroll
        for (int i = 0; i < LB; i++) {
            int v = tid + i * NT;
            if (TRANSB) {
                int n = v >> 2, kq = v & 3;
                cp16(smem_u32(&Bs[buf][TRANSB ? n : 0][kq * 4]),
                     &Bm[(size_t)(n0 + n) * ldb + k0 + kq * 4]);
            } else {
                int nq = v & (BN / 4 - 1), k = v / (BN / 4);
                cp16(smem_u32(&Bs[buf][TRANSB ? 0 : k][nq * 4]),
                     &Bm[(size_t)(k0 + k) * ldb + n0 + nq * 4]);
            }
        }
    };

    float acc[MT][NTL][4];
    #pragma unroll
    for (int i = 0; i < MT; i++)
        #pragma unroll
        for (int j = 0; j < NTL; j++)
            #pragma unroll
            for (int c = 0; c < 4; c++) acc[i][j][c] = 0.f;

    issue(0, 0); cp_commit();
    int cur = 0;
    for (int k0 = 0; k0 < K; k0 += BK) {
        cp_wait0();
        __syncthreads();
        bool more = (k0 + BK) < K;
        if (more) { issue(cur ^ 1, k0 + BK); cp_commit(); }

        #pragma unroll
        for (int ks = 0; ks < BK; ks += 8) {
            float af[MT][4], bf[NTL][2];
            #pragma unroll
            for (int mt = 0; mt < MT; mt++) {
                int rb0 = warpM * WM + mt * 16;
                af[mt][0] = As[cur][rb0 + gid    ][ks + tig];
                af[mt][1] = As[cur][rb0 + gid + 8][ks + tig];
                af[mt][2] = As[cur][rb0 + gid    ][ks + tig + 4];
                af[mt][3] = As[cur][rb0 + gid + 8][ks + tig + 4];
            }
            #pragma unroll
            for (int nt = 0; nt < NTL; nt++) {
                int cb0 = warpN * WN + nt * 8;
                if (TRANSB) {
                    bf[nt][0] = Bs[cur][TRANSB ? (cb0 + gid) : 0][ks + tig];
                    bf[nt][1] = Bs[cur][TRANSB ? (cb0 + gid) : 0][ks + tig + 4];
                } else {
                    bf[nt][0] = Bs[cur][TRANSB ? 0 : (ks + tig)    ][cb0 + gid];
                    bf[nt][1] = Bs[cur][TRANSB ? 0 : (ks + tig + 4)][cb0 + gid];
                }
            }
            #pragma unroll
            for (int mt = 0; mt < MT; mt++)
                #pragma unroll
                for (int nt = 0; nt < NTL; nt++)
                    mma_tf32(acc[mt][nt][0], acc[mt][nt][1],
                             acc[mt][nt][2], acc[mt][nt][3],
                             af[mt][0], af[mt][1], af[mt][2], af[mt][3],
                             bf[nt][0], bf[nt][1]);
        }
        cur ^= 1;
        __syncthreads();
    }

    #pragma unroll
    for (int mt = 0; mt < MT; mt++) {
        int row = m0 + warpM * WM + mt * 16 + gid;
        #pragma unroll
        for (int nt = 0; nt < NTL; nt++) {
            int col = n0 + warpN * WN + nt * 8 + tig * 2;
            float v0 = acc[mt][nt][0] * alpha;
            float v1 = acc[mt][nt][1] * alpha;
            float v2 = acc[mt][nt][2] * alpha;
            float v3 = acc[mt][nt][3] * alpha;
            if (bias) {
                float b0v = bias[col], b1v = bias[col + 1];
                v0 += b0v; v1 += b1v; v2 += b0v; v3 += b1v;
            }
            if (ACT == 1) {
                v0 = gelu_exact(v0); v1 = gelu_exact(v1);
                v2 = gelu_exact(v2); v3 = gelu_exact(v3);
            }
            *(float2*)&C[(size_t)row * ldc + col]       = make_float2(v0, v1);
            *(float2*)&C[(size_t)(row + 8) * ldc + col] = make_float2(v2, v3);
        }
    }
}

// ---------------- fused copy + layernorm (layer 0 entry) --------------------
__global__ void copy_ln_k(const float* __restrict__ xin, float* __restrict__ X,
                          const float* __restrict__ g, const float* __restrict__ b,
                          float* __restrict__ out)
{
    int row = blockIdx.x, tid = threadIdx.x;
    __shared__ float s[256];
    float v = xin[(size_t)row * D_ + tid];
    X[(size_t)row * D_ + tid] = v;
    s[tid] = v; __syncthreads();
    for (int st = 128; st > 0; st >>= 1) { if (tid < st) s[tid] += s[tid + st]; __syncthreads(); }
    float mu = s[0] * (1.f / D_);
    __syncthreads();
    float d = v - mu;
    s[tid] = d * d; __syncthreads();
    for (int st = 128; st > 0; st >>= 1) { if (tid < st) s[tid] += s[tid + st]; __syncthreads(); }
    float var = s[0] * (1.f / D_);
    out[(size_t)row * D_ + tid] = d * rsqrtf(var + EPS_) * g[tid] + b[tid];
}

// ---------------- fused scale + layernorm -----------------------------------
__global__ void scale_ln_k(float* __restrict__ X, const float* __restrict__ gate,
                           const float* __restrict__ g, const float* __restrict__ b,
                           float* __restrict__ out)
{
    int row = blockIdx.x, tid = threadIdx.x;
    int bb = row >> 10;
    __shared__ float s[256];
    float v = X[(size_t)row * D_ + tid] * gate[bb * D_ + tid];
    X[(size_t)row * D_ + tid] = v;
    s[tid] = v; __syncthreads();
    for (int st = 128; st > 0; st >>= 1) { if (tid < st) s[tid] += s[tid + st]; __syncthreads(); }
    float mu = s[0] * (1.f / D_);
    __syncthreads();
    float d = v - mu;
    s[tid] = d * d; __syncthreads();
    for (int st = 128; st > 0; st >>= 1) { if (tid < st) s[tid] += s[tid + st]; __syncthreads(); }
    float var = s[0] * (1.f / D_);
    out[(size_t)row * D_ + tid] = d * rsqrtf(var + EPS_) * g[tid] + b[tid];
}

// ---------------- residual add fused with column-sum ------------------------
__global__ void add_colsum_k(float* __restrict__ X, const float* __restrict__ y,
                             float* __restrict__ meanbuf)
{
    int b  = blockIdx.x >> 3;
    int n0 = (blockIdx.x & 7) * 128;
    int d  = threadIdx.x;
    size_t base = ((size_t)b * N_ + n0) * D_ + d;
    float acc = 0.f;
    #pragma unroll 8
    for (int r = 0; r < 128; r++) {
        size_t idx = base + (size_t)r * D_;
        float v = X[idx] + y[idx];
        X[idx] = v;
        acc += v;
    }
    atomicAdd(&meanbuf[b * D_ + d], acc);
}

__global__ void zero_k(float* __restrict__ p, int n)
{
    int idx = blockIdx.x * 256 + threadIdx.x;
    if (idx < n) p[idx] = 0.f;
}

// SE gate: s = sigmoid(relu(mean @ w1) @ w2); one block per batch
__global__ void gate_k(const float* __restrict__ meanbuf, const float* __restrict__ w1,
                       const float* __restrict__ w2, float* __restrict__ gatebuf)
{
    int b = blockIdx.x, tid = threadIdx.x;
    __shared__ float m[D_];
    __shared__ float t[D_ / 4];
    m[tid] = meanbuf[b * D_ + tid] * (1.f / N_);
    __syncthreads();
    if (tid < D_ / 4) {
        float acc = 0.f;
        #pragma unroll 8
        for (int d = 0; d < D_; d++) acc += m[d] * w1[d * (D_ / 4) + tid];
        t[tid] = fmaxf(acc, 0.f);
    }
    __syncthreads();
    float acc = 0.f;
    #pragma unroll 8
    for (int j = 0; j < D_ / 4; j++) acc += t[j] * w2[j * D_ + tid];
    gatebuf[b * D_ + tid] = 1.f / (1.f + expf(-acc));
}

__global__ void scale_k(float* __restrict__ x, const float* __restrict__ gate)
{
    int idx = blockIdx.x * 256 + threadIdx.x;
    int d = idx & (D_ - 1);
    int b = idx / (N_ * D_);
    x[idx] *= gate[b * D_ + d];
}

// depthwise 1x3 conv over tokens + center-tap conv + BN(eval) + exact gelu
__global__ void conv_k(const float* __restrict__ y, const float* __restrict__ wh,
                       const float* __restrict__ bh, const float* __restrict__ wv,
                       const float* __restrict__ bv, const float* __restrict__ bng,
                       const float* __restrict__ bnb, const float* __restrict__ bnm,
                       const float* __restrict__ bnv, float* __restrict__ out)
{
    int idx = blockIdx.x * 256 + threadIdx.x;
    int m = idx & (M_ - 1);
    int n = (idx / M_) & (N_ - 1);
    float y0 = y[idx];
    float ym = (n > 0)      ? y[idx - M_] : 0.f;
    float yp = (n < N_ - 1) ? y[idx + M_] : 0.f;
    float ch = wh[m * 3 + 0] * ym + wh[m * 3 + 1] * y0 + wh[m * 3 + 2] * yp + bh[m];
    float cv = wv[m * 3 + 1] * y0 + bv[m];
    float zz = ch + cv;
    zz = (zz - bnm[m]) * rsqrtf(bnv[m] + EPS_) * bng[m] + bnb[m];
    out[idx] = gelu_exact(zz);
}

// ---------------- driver -----------------------------------------------------
extern "C" void kernel_launch(void* const* d_in, const int* in_sizes, int n_in,
                              void* d_out, int out_size)
{
    const float* x_in  = (const float*)d_in[0];
    const float* ln1_g = (const float*)d_in[1];
    const float* ln1_b = (const float*)d_in[2];
    const float* w_qkv = (const float*)d_in[3];
    const float* w_out = (const float*)d_in[4];
    const float* b_out = (const float*)d_in[5];
    const float* ln2_g = (const float*)d_in[6];
    const float* ln2_b = (const float*)d_in[7];
    const float* w_fc1 = (const float*)d_in[8];
    const float* b_fc1 = (const float*)d_in[9];
    const float* wh    = (const float*)d_in[10];
    const float* bh    = (const float*)d_in[11];
    const float* wv    = (const float*)d_in[12];
    const float* bv    = (const float*)d_in[13];
    const float* bn_g  = (const float*)d_in[14];
    const float* bn_b  = (const float*)d_in[15];
    const float* bn_m  = (const float*)d_in[16];
    const float* bn_v  = (const float*)d_in[17];
    const float* w_fc2 = (const float*)d_in[18];
    const float* b_fc2 = (const float*)d_in[19];
    const float* ls_w1 = (const float*)d_in[20];
    const float* ls_w2 = (const float*)d_in[21];

    float *ph, *pqkv, *po, *py, *pt1, *pt2, *pmean, *pgate;
    cudaGetSymbolAddress((void**)&ph,    g_h);
    cudaGetSymbolAddress((void**)&pqkv,  g_qkv);
    cudaGetSymbolAddress((void**)&po,    g_o);
    cudaGetSymbolAddress((void**)&py,    g_y);
    cudaGetSymbolAddress((void**)&pt1,   g_t1);
    cudaGetSymbolAddress((void**)&pt2,   g_t2);
    cudaGetSymbolAddress((void**)&pmean, g_mean);
    cudaGetSymbolAddress((void**)&pgate, g_gate);

    cudaFuncSetAttribute(flash_k, cudaFuncAttributeMaxDynamicSharedMemorySize,
                         FLASH_SMEM_BYTES);

    float* X = (float*)d_out;
    const int ROWS = B_ * N_;   // 8192

    for (int l = 0; l < 2; l++) {
        const float* w_qkv_l = w_qkv + (size_t)l * D_ * 3 * D_;
        const float* w_out_l = w_out + (size_t)l * D_ * D_;
        const float* b_out_l = b_out + (size_t)l * D_;
        const float* w_fc1_l = w_fc1 + (size_t)l * D_ * M_;
        const float* b_fc1_l = b_fc1 + (size_t)l * M_;
        const float* w_fc2_l = w_fc2 + (size_t)l * M_ * D_;
        const float* b_fc2_l = b_fc2 + (size_t)l * D_;
        const float* w1_l    = ls_w1 + (size_t)l * D_ * (D_/4);
        const float* w2_l    = ls_w2 + (size_t)l * (D_/4) * D_;

        // --- MHSA ---  (h = LN1(X); layer 0 fuses the initial copy)
        if (l == 0)
            copy_ln_k<<<ROWS, 256>>>(x_in, X, ln1_g, ln1_b, ph);

        // qkv = h @ w_qkv   grid 6x64 = 384
        gemm4_k<128,128,false,0><<<dim3((3*D_)/128, ROWS/128, 1), 128>>>(
            ph, D_, 0, 0, w_qkv_l, 3*D_, 0, 0, pqkv, 3*D_, 0, 0,
            nullptr, D_, 1, 1.f);

        // fused attention: o = softmax(q k^T / 8) v    grid 8x32 = 256
        flash_k<<<dim3(1, N_/FBM, B_*H_), FWARPS*32, FLASH_SMEM_BYTES>>>(pqkv, po);

        // y = o @ w_out + b_out   grid 4x64 = 256
        gemm4_k<128,64,false,0><<<dim3(D_/64, ROWS/128, 1), 128>>>(
            po, D_, 0, 0, w_out_l, D_, 0, 0, py, D_, 0, 0,
            b_out_l, D_, 1, 1.f);

        // lsrc #1 (fused)
        zero_k<<<(B_*D_ + 255)/256, 256>>>(pmean, B_*D_);
        add_colsum_k<<<B_ * (N_/128), 256>>>(X, py, pmean);
        gate_k<<<B_, 256>>>(pmean, w1_l, w2_l, pgate);
        scale_ln_k<<<ROWS, 256>>>(X, pgate, ln2_g + l * D_, ln2_b + l * D_, ph);

        // --- MLP ---
        // t1 = gelu(h @ w_fc1 + b_fc1)   grid 4x64 = 256
        gemm4_k<128,128,false,1><<<dim3(M_/128, ROWS/128, 1), 128>>>(
            ph, D_, 0, 0, w_fc1_l, M_, 0, 0, pt1, M_, 0, 0,
            b_fc1_l, D_, 1, 1.f);

        conv_k<<<(B_*N_*M_)/256, 256>>>(
            pt1, wh + (size_t)l*M_*3, bh + (size_t)l*M_,
            wv + (size_t)l*M_*3, bv + (size_t)l*M_,
            bn_g + (size_t)l*M_, bn_b + (size_t)l*M_,
            bn_m + (size_t)l*M_, bn_v + (size_t)l*M_, pt2);

        // y = t2 @ w_fc2 + b_fc2   grid 4x64 = 256
        gemm4_k<128,64,false,0><<<dim3(D_/64, ROWS/128, 1), 128>>>(
            pt2, M_, 0, 0, w_fc2_l, D_, 0, 0, py, D_, 0, 0,
            b_fc2_l, M_, 1, 1.f);

        // lsrc #2 (fused); last one has no following LN
        zero_k<<<(B_*D_ + 255)/256, 256>>>(pmean, B_*D_);
        add_colsum_k<<<B_ * (N_/128), 256>>>(X, py, pmean);
        gate_k<<<B_, 256>>>(pmean, w1_l, w2_l, pgate);
        if (l + 1 < 2)
            scale_ln_k<<<ROWS, 256>>>(X, pgate, ln1_g + (l+1) * D_, ln1_b + (l+1) * D_, ph);
        else
            scale_k<<<(B_*N_*D_)/256, 256>>>(X, pgate);
    }
}

// round 7
// speedup vs baseline: 1.0474x; 1.0474x over previous
#include <cuda_runtime.h>
#include <math.h>
#include <stdint.h>

#define B_  8
#define N_  1024
#define D_  256
#define H_  4
#define DH_ 64
#define M_  512
#define EPS_ 1e-5f

// ---------------- scratch (device globals; no allocations allowed) ----------
__device__ float g_h[B_*N_*D_];                 // LN output
__device__ float g_qkv[B_*N_*3*D_];             // qkv
__device__ float g_o[B_*N_*D_];                 // attn out
__device__ float g_y[B_*N_*D_];                 // branch output
__device__ float g_t1[B_*N_*M_];                // fc1/gelu out
__device__ float g_t2[B_*N_*M_];                // conv/bn/gelu out
__device__ float g_meanp[B_*8*D_];              // colsum partials
__device__ float g_gate[B_*D_];

__device__ __forceinline__ float gelu_exact(float v) {
    return 0.5f * v * (1.f + erff(v * 0.70710678118654752f));
}

__device__ __forceinline__ void mma_tf32(float& c0, float& c1, float& c2, float& c3,
                                         float a0, float a1, float a2, float a3,
                                         float b0, float b1)
{
    asm volatile(
        "mma.sync.aligned.m16n8k8.row.col.f32.tf32.tf32.f32 "
        "{%0,%1,%2,%3},{%4,%5,%6,%7},{%8,%9},{%0,%1,%2,%3};"
        : "+f"(c0), "+f"(c1), "+f"(c2), "+f"(c3)
        : "r"(__float_as_uint(a0)), "r"(__float_as_uint(a1)),
          "r"(__float_as_uint(a2)), "r"(__float_as_uint(a3)),
          "r"(__float_as_uint(b0)), "r"(__float_as_uint(b1)));
}

__device__ __forceinline__ void cp16(uint32_t dst, const void* src) {
    asm volatile("cp.async.cg.shared.global [%0], [%1], 16;" :: "r"(dst), "l"(src));
}
__device__ __forceinline__ void cp_commit() {
    asm volatile("cp.async.commit_group;" ::: "memory");
}
__device__ __forceinline__ void cp_wait0() {
    asm volatile("cp.async.wait_group 0;" ::: "memory");
}
__device__ __forceinline__ uint32_t smem_u32(const void* p) {
    return (uint32_t)__cvta_generic_to_shared(p);
}

// ---------------- flash attention (R5 measured-good config) ------------------
// One CTA = 64 query rows of one (b,h). 4 warps x 16 rows. 16 KV tiles of 64,
// double-buffered cp.async. Online softmax in registers.
#define FBM 64
#define FBN 64

struct FlashSmem {
    float Q[FBM][68];
    float K[2][FBN][68];
    float V[2][FBN][72];
    float P[4][16][68];
};
#define FLASH_SMEM_BYTES ((int)sizeof(FlashSmem))

__global__ __launch_bounds__(128)
void flash_k(const float* __restrict__ qkv, float* __restrict__ Og)
{
    extern __shared__ float smem_raw[];
    FlashSmem& S = *(FlashSmem*)smem_raw;

    const int bh = blockIdx.z;
    const int b = bh >> 2, h = bh & 3;
    const int m0 = blockIdx.y * FBM;
    const int tid  = threadIdx.x;
    const int warp = tid >> 5, lane = tid & 31;
    const int gid  = lane >> 2, tig = lane & 3;

    const float* qb = qkv + ((size_t)b * N_) * (3*D_) + h * DH_;

    #pragma unroll
    for (int i = 0; i < 8; i++) {
        int v = tid + i * 128;
        int r = v >> 4, dq = v & 15;
        float4 t = *(const float4*)&qb[(size_t)(m0 + r) * (3*D_) + dq * 4];
        t.x *= 0.125f; t.y *= 0.125f; t.z *= 0.125f; t.w *= 0.125f;
        *(float4*)&S.Q[r][dq * 4] = t;
    }

    auto issue = [&](int buf, int t) {
        int n0 = t * FBN;
        const float* kb = qkv + ((size_t)b * N_ + n0) * (3*D_) + D_ + h * DH_;
        const float* vb = kb + D_;
        #pragma unroll
        for (int i = 0; i < 8; i++) {
            int v = tid + i * 128;
            int r = v >> 4, dq = v & 15;
            cp16(smem_u32(&S.K[buf][r][dq * 4]), &kb[(size_t)r * (3*D_) + dq * 4]);
            cp16(smem_u32(&S.V[buf][r][dq * 4]), &vb[(size_t)r * (3*D_) + dq * 4]);
        }
    };

    float mr0 = -1e30f, mr1 = -1e30f, l0 = 0.f, l1 = 0.f;
    float o[8][4];
    #pragma unroll
    for (int nt = 0; nt < 8; nt++)
        #pragma unroll
        for (int c = 0; c < 4; c++) o[nt][c] = 0.f;

    const int qrow = warp * 16 + gid;

    issue(0, 0); cp_commit();
    for (int t = 0; t < N_ / FBN; t++) {
        int cur = t & 1;
        cp_wait0();
        __syncthreads();
        if (t + 1 < N_ / FBN) { issue(cur ^ 1, t + 1); cp_commit(); }

        float s[8][4];
        #pragma unroll
        for (int nt = 0; nt < 8; nt++)
            #pragma unroll
            for (int c = 0; c < 4; c++) s[nt][c] = 0.f;

        #pragma unroll
        for (int ks = 0; ks < DH_; ks += 8) {
            float a0 = S.Q[qrow    ][ks + tig];
            float a1 = S.Q[qrow + 8][ks + tig];
            float a2 = S.Q[qrow    ][ks + tig + 4];
            float a3 = S.Q[qrow + 8][ks + tig + 4];
            #pragma unroll
            for (int nt = 0; nt < 8; nt++) {
                float b0 = S.K[cur][nt * 8 + gid][ks + tig];
                float b1 = S.K[cur][nt * 8 + gid][ks + tig + 4];
                mma_tf32(s[nt][0], s[nt][1], s[nt][2], s[nt][3],
                         a0, a1, a2, a3, b0, b1);
            }
        }

        float rm0 = -1e30f, rm1 = -1e30f;
        #pragma unroll
        for (int nt = 0; nt < 8; nt++) {
            rm0 = fmaxf(rm0, fmaxf(s[nt][0], s[nt][1]));
            rm1 = fmaxf(rm1, fmaxf(s[nt][2], s[nt][3]));
        }
        rm0 = fmaxf(rm0, __shfl_xor_sync(0xffffffff, rm0, 1));
        rm0 = fmaxf(rm0, __shfl_xor_sync(0xffffffff, rm0, 2));
        rm1 = fmaxf(rm1, __shfl_xor_sync(0xffffffff, rm1, 1));
        rm1 = fmaxf(rm1, __shfl_xor_sync(0xffffffff, rm1, 2));

        float mn0 = fmaxf(mr0, rm0), mn1 = fmaxf(mr1, rm1);
        float sc0 = __expf(mr0 - mn0), sc1 = __expf(mr1 - mn1);
        mr0 = mn0; mr1 = mn1;

        float rs0 = 0.f, rs1 = 0.f;
        #pragma unroll
        for (int nt = 0; nt < 8; nt++) {
            s[nt][0] = __expf(s[nt][0] - mn0);
            s[nt][1] = __expf(s[nt][1] - mn0);
            s[nt][2] = __expf(s[nt][2] - mn1);
            s[nt][3] = __expf(s[nt][3] - mn1);
            rs0 += s[nt][0] + s[nt][1];
            rs1 += s[nt][2] + s[nt][3];
        }
        rs0 += __shfl_xor_sync(0xffffffff, rs0, 1);
        rs0 += __shfl_xor_sync(0xffffffff, rs0, 2);
        rs1 += __shfl_xor_sync(0xffffffff, rs1, 1);
        rs1 += __shfl_xor_sync(0xffffffff, rs1, 2);
        l0 = l0 * sc0 + rs0;
        l1 = l1 * sc1 + rs1;

        #pragma unroll
        for (int nt = 0; nt < 8; nt++) {
            o[nt][0] *= sc0; o[nt][1] *= sc0;
            o[nt][2] *= sc1; o[nt][3] *= sc1;
        }

        #pragma unroll
        for (int nt = 0; nt < 8; nt++) {
            S.P[warp][gid    ][nt * 8 + tig * 2    ] = s[nt][0];
            S.P[warp][gid    ][nt * 8 + tig * 2 + 1] = s[nt][1];
            S.P[warp][gid + 8][nt * 8 + tig * 2    ] = s[nt][2];
            S.P[warp][gid + 8][nt * 8 + tig * 2 + 1] = s[nt][3];
        }
        __syncwarp();

        #pragma unroll
        for (int ks = 0; ks < FBN; ks += 8) {
            float a0 = S.P[warp][gid    ][ks + tig];
            float a1 = S.P[warp][gid + 8][ks + tig];
            float a2 = S.P[warp][gid    ][ks + tig + 4];
            float a3 = S.P[warp][gid + 8][ks + tig + 4];
            #pragma unroll
            for (int nt = 0; nt < 8; nt++) {
                float b0 = S.V[cur][ks + tig    ][nt * 8 + gid];
                float b1 = S.V[cur][ks + tig + 4][nt * 8 + gid];
                mma_tf32(o[nt][0], o[nt][1], o[nt][2], o[nt][3],
                         a0, a1, a2, a3, b0, b1);
            }
        }
        __syncwarp();
    }

    float inv0 = 1.f / l0, inv1 = 1.f / l1;
    int r0 = m0 + qrow;
    float* ob0 = Og + ((size_t)b * N_ + r0    ) * D_ + h * DH_;
    float* ob1 = Og + ((size_t)b * N_ + r0 + 8) * D_ + h * DH_;
    #pragma unroll
    for (int nt = 0; nt < 8; nt++) {
        int col = nt * 8 + tig * 2;
        *(float2*)&ob0[col] = make_float2(o[nt][0] * inv0, o[nt][1] * inv0);
        *(float2*)&ob1[col] = make_float2(o[nt][2] * inv1, o[nt][3] * inv1);
    }
}

// ---------------- dense tensor-core GEMM v5 (tf32, cp.async) -----------------
// C = A @ B (+bias) (+gelu). WSM x WSN warps, warp tile (BM/WSM)x(BN/WSN).
// A m-major [BM][20]; B k-major [BK][BN+8]. Double-buffered cp.async.
template<int BM, int BN, int WSM, int WSN, int ACT>
__global__ __launch_bounds__(WSM*WSN*32)
void gemm5_k(const float* __restrict__ A, int lda,
             const float* __restrict__ Bm, int ldb,
             float* __restrict__ C, int ldc,
             const float* __restrict__ bias, int K)
{
    constexpr int BK = 16;
    constexpr int NT = WSM * WSN * 32;
    constexpr int WM = BM / WSM, WN = BN / WSN;
    constexpr int MT = WM / 16, NTL = WN / 8;
    constexpr int SA = BK + 4;
    constexpr int LA = BM * BK / (4 * NT);
    constexpr int LB = BN * BK / (4 * NT);

    __shared__ __align__(16) float As[2][BM][SA];
    __shared__ __align__(16) float Bs[2][BK][BN + 8];

    const int m0 = blockIdx.y * BM;
    const int n0 = blockIdx.x * BN;
    const int tid   = threadIdx.x;
    const int warp  = tid >> 5;
    const int lane  = tid & 31;
    const int gid   = lane >> 2;
    const int tig   = lane & 3;
    const int warpM = warp / WSN;
    const int warpN = warp % WSN;

    auto issue = [&](int buf, int k0) {
        #pragma unroll
        for (int i = 0; i < LA; i++) {
            int v = tid + i * NT;
            int m = v >> 2, kq = v & 3;
            cp16(smem_u32(&As[buf][m][kq * 4]),
                 &A[(size_t)(m0 + m) * lda + k0 + kq * 4]);
        }
        #pragma unroll
        for (int i = 0; i < LB; i++) {
            int v = tid + i * NT;
            int nq = v % (BN / 4), k = v / (BN / 4);
            cp16(smem_u32(&Bs[buf][k][nq * 4]),
                 &Bm[(size_t)(k0 + k) * ldb + n0 + nq * 4]);
        }
    };

    float acc[MT][NTL][4];
    #pragma unroll
    for (int i = 0; i < MT; i++)
        #pragma unroll
        for (int j = 0; j < NTL; j++)
            #pragma unroll
            for (int c = 0; c < 4; c++) acc[i][j][c] = 0.f;

    issue(0, 0); cp_commit();
    int cur = 0;
    for (int k0 = 0; k0 < K; k0 += BK) {
        cp_wait0();
        __syncthreads();
        bool more = (k0 + BK) < K;
        if (more) { issue(cur ^ 1, k0 + BK); cp_commit(); }

        #pragma unroll
        for (int ks = 0; ks < BK; ks += 8) {
            float af[MT][4], bf[NTL][2];
            #pragma unroll
            for (int mt = 0; mt < MT; mt++) {
                int rb0 = warpM * WM + mt * 16;
                af[mt][0] = As[cur][rb0 + gid    ][ks + tig];
                af[mt][1] = As[cur][rb0 + gid + 8][ks + tig];
                af[mt][2] = As[cur][rb0 + gid    ][ks + tig + 4];
                af[mt][3] = As[cur][rb0 + gid + 8][ks + tig + 4];
            }
            #pragma unroll
            for (int nt = 0; nt < NTL; nt++) {
                int cb0 = warpN * WN + nt * 8;
                bf[nt][0] = Bs[cur][ks + tig    ][cb0 + gid];
                bf[nt][1] = Bs[cur][ks + tig + 4][cb0 + gid];
            }
            #pragma unroll
            for (int mt = 0; mt < MT; mt++)
                #pragma unroll
                for (int nt = 0; nt < NTL; nt++)
                    mma_tf32(acc[mt][nt][0], acc[mt][nt][1],
                             acc[mt][nt][2], acc[mt][nt][3],
                             af[mt][0], af[mt][1], af[mt][2], af[mt][3],
                             bf[nt][0], bf[nt][1]);
        }
        cur ^= 1;
        __syncthreads();
    }

    #pragma unroll
    for (int mt = 0; mt < MT; mt++) {
        int row = m0 + warpM * WM + mt * 16 + gid;
        #pragma unroll
        for (int nt = 0; nt < NTL; nt++) {
            int col = n0 + warpN * WN + nt * 8 + tig * 2;
            float v0 = acc[mt][nt][0];
            float v1 = acc[mt][nt][1];
            float v2 = acc[mt][nt][2];
            float v3 = acc[mt][nt][3];
            if (bias) {
                float b0v = bias[col], b1v = bias[col + 1];
                v0 += b0v; v1 += b1v; v2 += b0v; v3 += b1v;
            }
            if (ACT == 1) {
                v0 = gelu_exact(v0); v1 = gelu_exact(v1);
                v2 = gelu_exact(v2); v3 = gelu_exact(v3);
            }
            *(float2*)&C[(size_t)row * ldc + col]       = make_float2(v0, v1);
            *(float2*)&C[(size_t)(row + 8) * ldc + col] = make_float2(v2, v3);
        }
    }
}

// ---------------- fused copy + layernorm (layer 0 entry) --------------------
__global__ void copy_ln_k(const float* __restrict__ xin, float* __restrict__ X,
                          const float* __restrict__ g, const float* __restrict__ b,
                          float* __restrict__ out)
{
    int row = blockIdx.x, tid = threadIdx.x;
    __shared__ float s[256];
    float v = xin[(size_t)row * D_ + tid];
    X[(size_t)row * D_ + tid] = v;
    s[tid] = v; __syncthreads();
    for (int st = 128; st > 0; st >>= 1) { if (tid < st) s[tid] += s[tid + st]; __syncthreads(); }
    float mu = s[0] * (1.f / D_);
    __syncthreads();
    float d = v - mu;
    s[tid] = d * d; __syncthreads();
    for (int st = 128; st > 0; st >>= 1) { if (tid < st) s[tid] += s[tid + st]; __syncthreads(); }
    float var = s[0] * (1.f / D_);
    out[(size_t)row * D_ + tid] = d * rsqrtf(var + EPS_) * g[tid] + b[tid];
}

// ---------------- fused scale + layernorm -----------------------------------
__global__ void scale_ln_k(float* __restrict__ X, const float* __restrict__ gate,
                           const float* __restrict__ g, const float* __restrict__ b,
                           float* __restrict__ out)
{
    int row = blockIdx.x, tid = threadIdx.x;
    int bb = row >> 10;
    __shared__ float s[256];
    float v = X[(size_t)row * D_ + tid] * gate[bb * D_ + tid];
    X[(size_t)row * D_ + tid] = v;
    s[tid] = v; __syncthreads();
    for (int st = 128; st > 0; st >>= 1) { if (tid < st) s[tid] += s[tid + st]; __syncthreads(); }
    float mu = s[0] * (1.f / D_);
    __syncthreads();
    float d = v - mu;
    s[tid] = d * d; __syncthreads();
    for (int st = 128; st > 0; st >>= 1) { if (tid < st) s[tid] += s[tid + st]; __syncthreads(); }
    float var = s[0] * (1.f / D_);
    out[(size_t)row * D_ + tid] = d * rsqrtf(var + EPS_) * g[tid] + b[tid];
}

// -------- residual add fused with column-sum partials (no atomics) ----------
__global__ void add_colsum_k(float* __restrict__ X, const float* __restrict__ y,
                             float* __restrict__ meanp)
{
    int b  = blockIdx.x >> 3;
    int ch = blockIdx.x & 7;
    int d  = threadIdx.x;
    size_t base = ((size_t)b * N_ + ch * 128) * D_ + d;
    float acc = 0.f;
    #pragma unroll 8
    for (int r = 0; r < 128; r++) {
        size_t idx = base + (size_t)r * D_;
        float v = X[idx] + y[idx];
        X[idx] = v;
        acc += v;
    }
    meanp[((size_t)b * 8 + ch) * D_ + d] = acc;
}

// SE gate: s = sigmoid(relu(mean @ w1) @ w2); one block per batch
__global__ void gate_k(const float* __restrict__ meanp, const float* __restrict__ w1,
                       const float* __restrict__ w2, float* __restrict__ gatebuf)
{
    int b = blockIdx.x, tid = threadIdx.x;
    __shared__ float m[D_];
    __shared__ float t[D_ / 4];
    float acc0 = 0.f;
    #pragma unroll
    for (int c = 0; c < 8; c++) acc0 += meanp[((size_t)b * 8 + c) * D_ + tid];
    m[tid] = acc0 * (1.f / N_);
    __syncthreads();
    if (tid < D_ / 4) {
        float acc = 0.f;
        #pragma unroll 8
        for (int d = 0; d < D_; d++) acc += m[d] * w1[d * (D_ / 4) + tid];
        t[tid] = fmaxf(acc, 0.f);
    }
    __syncthreads();
    float acc = 0.f;
    #pragma unroll 8
    for (int j = 0; j < D_ / 4; j++) acc += t[j] * w2[j * D_ + tid];
    gatebuf[b * D_ + tid] = 1.f / (1.f + expf(-acc));
}

__global__ void scale_k(float* __restrict__ x, const float* __restrict__ gate)
{
    int idx = blockIdx.x * 256 + threadIdx.x;
    int d = idx & (D_ - 1);
    int b = idx / (N_ * D_);
    x[idx] *= gate[b * D_ + d];
}

// depthwise 1x3 conv over tokens + center-tap conv + BN(eval) + exact gelu
__global__ void conv_k(const float* __restrict__ y, const float* __restrict__ wh,
                       const float* __restrict__ bh, const float* __restrict__ wv,
                       const float* __restrict__ bv, const float* __restrict__ bng,
                       const float* __restrict__ bnb, const float* __restrict__ bnm,
                       const float* __restrict__ bnv, float* __restrict__ out)
{
    int idx = blockIdx.x * 256 + threadIdx.x;
    int m = idx & (M_ - 1);
    int n = (idx / M_) & (N_ - 1);
    float y0 = y[idx];
    float ym = (n > 0)      ? y[idx - M_] : 0.f;
    float yp = (n < N_ - 1) ? y[idx + M_] : 0.f;
    float ch = wh[m * 3 + 0] * ym + wh[m * 3 + 1] * y0 + wh[m * 3 + 2] * yp + bh[m];
    float cv = wv[m * 3 + 1] * y0 + bv[m];
    float zz = ch + cv;
    zz = (zz - bnm[m]) * rsqrtf(bnv[m] + EPS_) * bng[m] + bnb[m];
    out[idx] = gelu_exact(zz);
}

// ---------------- driver -----------------------------------------------------
extern "C" void kernel_launch(void* const* d_in, const int* in_sizes, int n_in,
                              void* d_out, int out_size)
{
    const float* x_in  = (const float*)d_in[0];
    const float* ln1_g = (const float*)d_in[1];
    const float* ln1_b = (const float*)d_in[2];
    const float* w_qkv = (const float*)d_in[3];
    const float* w_out = (const float*)d_in[4];
    const float* b_out = (const float*)d_in[5];
    const float* ln2_g = (const float*)d_in[6];
    const float* ln2_b = (const float*)d_in[7];
    const float* w_fc1 = (const float*)d_in[8];
    const float* b_fc1 = (const float*)d_in[9];
    const float* wh    = (const float*)d_in[10];
    const float* bh    = (const float*)d_in[11];
    const float* wv    = (const float*)d_in[12];
    const float* bv    = (const float*)d_in[13];
    const float* bn_g  = (const float*)d_in[14];
    const float* bn_b  = (const float*)d_in[15];
    const float* bn_m  = (const float*)d_in[16];
    const float* bn_v  = (const float*)d_in[17];
    const float* w_fc2 = (const float*)d_in[18];
    const float* b_fc2 = (const float*)d_in[19];
    const float* ls_w1 = (const float*)d_in[20];
    const float* ls_w2 = (const float*)d_in[21];

    float *ph, *pqkv, *po, *py, *pt1, *pt2, *pmeanp, *pgate;
    cudaGetSymbolAddress((void**)&ph,     g_h);
    cudaGetSymbolAddress((void**)&pqkv,   g_qkv);
    cudaGetSymbolAddress((void**)&po,     g_o);
    cudaGetSymbolAddress((void**)&py,     g_y);
    cudaGetSymbolAddress((void**)&pt1,    g_t1);
    cudaGetSymbolAddress((void**)&pt2,    g_t2);
    cudaGetSymbolAddress((void**)&pmeanp, g_meanp);
    cudaGetSymbolAddress((void**)&pgate,  g_gate);

    cudaFuncSetAttribute(flash_k, cudaFuncAttributeMaxDynamicSharedMemorySize,
                         FLASH_SMEM_BYTES);

    float* X = (float*)d_out;
    const int ROWS = B_ * N_;   // 8192

    for (int l = 0; l < 2; l++) {
        const float* w_qkv_l = w_qkv + (size_t)l * D_ * 3 * D_;
        const float* w_out_l = w_out + (size_t)l * D_ * D_;
        const float* b_out_l = b_out + (size_t)l * D_;
        const float* w_fc1_l = w_fc1 + (size_t)l * D_ * M_;
        const float* b_fc1_l = b_fc1 + (size_t)l * M_;
        const float* w_fc2_l = w_fc2 + (size_t)l * M_ * D_;
        const float* b_fc2_l = b_fc2 + (size_t)l * D_;
        const float* w1_l    = ls_w1 + (size_t)l * D_ * (D_/4);
        const float* w2_l    = ls_w2 + (size_t)l * (D_/4) * D_;

        // --- MHSA ---  (h = LN1(X); layer 0 fuses the initial copy)
        if (l == 0)
            copy_ln_k<<<ROWS, 256>>>(x_in, X, ln1_g, ln1_b, ph);

        // qkv = h @ w_qkv   grid 6x64, 256 thr (8 warps)
        gemm5_k<128,128,2,4,0><<<dim3((3*D_)/128, ROWS/128, 1), 256>>>(
            ph, D_, w_qkv_l, 3*D_, pqkv, 3*D_, nullptr, D_);

        // fused attention   grid 32x128 = 512 CTAs
        flash_k<<<dim3(1, N_/FBM, B_*H_), 128, FLASH_SMEM_BYTES>>>(pqkv, po);

        // y = o @ w_out + b_out   grid 4x128 = 512 CTAs
        gemm5_k<64,64,2,2,0><<<dim3(D_/64, ROWS/64, 1), 128>>>(
            po, D_, w_out_l, D_, py, D_, b_out_l, D_);

        // lsrc #1 (fused, atomic-free)
        add_colsum_k<<<B_ * 8, 256>>>(X, py, pmeanp);
        gate_k<<<B_, 256>>>(pmeanp, w1_l, w2_l, pgate);
        scale_ln_k<<<ROWS, 256>>>(X, pgate, ln2_g + l * D_, ln2_b + l * D_, ph);

        // --- MLP ---
        // t1 = gelu(h @ w_fc1 + b_fc1)   grid 4x64, 256 thr
        gemm5_k<128,128,2,4,1><<<dim3(M_/128, ROWS/128, 1), 256>>>(
            ph, D_, w_fc1_l, M_, pt1, M_, b_fc1_l, D_);

        conv_k<<<(B_*N_*M_)/256, 256>>>(
            pt1, wh + (size_t)l*M_*3, bh + (size_t)l*M_,
            wv + (size_t)l*M_*3, bv + (size_t)l*M_,
            bn_g + (size_t)l*M_, bn_b + (size_t)l*M_,
            bn_m + (size_t)l*M_, bn_v + (size_t)l*M_, pt2);

        // y = t2 @ w_fc2 + b_fc2   grid 4x128 = 512 CTAs
        gemm5_k<64,64,2,2,0><<<dim3(D_/64, ROWS/64, 1), 128>>>(
            pt2, M_, w_fc2_l, D_, py, D_, b_fc2_l, M_);

        // lsrc #2 (fused); last one has no following LN
        add_colsum_k<<<B_ * 8, 256>>>(X, py, pmeanp);
        gate_k<<<B_, 256>>>(pmeanp, w1_l, w2_l, pgate);
        if (l + 1 < 2)
            scale_ln_k<<<ROWS, 256>>>(X, pgate, ln1_g + (l+1) * D_, ln1_b + (l+1) * D_, ph);
        else
            scale_k<<<(B_*N_*D_)/256, 256>>>(X, pgate);
    }
}

// round 8
// speedup vs baseline: 1.0672x; 1.0189x over previous
#include <cuda_runtime.h>
#include <math.h>
#include <stdint.h>

#define B_  8
#define N_  1024
#define D_  256
#define H_  4
#define DH_ 64
#define M_  512
#define EPS_ 1e-5f

// ---------------- scratch (device globals; no allocations allowed) ----------
__device__ float g_h[B_*N_*D_];                 // LN output
__device__ float g_qkv[B_*N_*3*D_];             // qkv
__device__ float g_o[B_*N_*D_];                 // attn out
__device__ float g_t1[B_*N_*M_];                // fc1/gelu out
__device__ float g_t2[B_*N_*M_];                // conv/bn/gelu out
__device__ float g_meanp[B_*8*D_];              // colsum partials
__device__ float g_gate[B_*D_];

__device__ __forceinline__ float gelu_exact(float v) {
    return 0.5f * v * (1.f + erff(v * 0.70710678118654752f));
}

__device__ __forceinline__ void mma_tf32(float& c0, float& c1, float& c2, float& c3,
                                         float a0, float a1, float a2, float a3,
                                         float b0, float b1)
{
    asm volatile(
        "mma.sync.aligned.m16n8k8.row.col.f32.tf32.tf32.f32 "
        "{%0,%1,%2,%3},{%4,%5,%6,%7},{%8,%9},{%0,%1,%2,%3};"
        : "+f"(c0), "+f"(c1), "+f"(c2), "+f"(c3)
        : "r"(__float_as_uint(a0)), "r"(__float_as_uint(a1)),
          "r"(__float_as_uint(a2)), "r"(__float_as_uint(a3)),
          "r"(__float_as_uint(b0)), "r"(__float_as_uint(b1)));
}

__device__ __forceinline__ void cp16(uint32_t dst, const void* src) {
    asm volatile("cp.async.cg.shared.global [%0], [%1], 16;" :: "r"(dst), "l"(src));
}
__device__ __forceinline__ void cp_commit() {
    asm volatile("cp.async.commit_group;" ::: "memory");
}
template<int N>
__device__ __forceinline__ void cp_wait() {
    asm volatile("cp.async.wait_group %0;" :: "n"(N) : "memory");
}
__device__ __forceinline__ uint32_t smem_u32(const void* p) {
    return (uint32_t)__cvta_generic_to_shared(p);
}

// ---------------- flash attention (split K/V waits) --------------------------
#define FBM 64
#define FBN 64

struct FlashSmem {
    float Q[FBM][68];
    float K[2][FBN][68];
    float V[2][FBN][72];
    float P[4][16][68];
};
#define FLASH_SMEM_BYTES ((int)sizeof(FlashSmem))

__global__ __launch_bounds__(128)
void flash_k(const float* __restrict__ qkv, float* __restrict__ Og)
{
    extern __shared__ float smem_raw[];
    FlashSmem& S = *(FlashSmem*)smem_raw;

    const int bh = blockIdx.z;
    const int b = bh >> 2, h = bh & 3;
    const int m0 = blockIdx.y * FBM;
    const int tid  = threadIdx.x;
    const int warp = tid >> 5, lane = tid & 31;
    const int gid  = lane >> 2, tig = lane & 3;

    const float* qb = qkv + ((size_t)b * N_) * (3*D_) + h * DH_;

    #pragma unroll
    for (int i = 0; i < 8; i++) {
        int v = tid + i * 128;
        int r = v >> 4, dq = v & 15;
        float4 t = *(const float4*)&qb[(size_t)(m0 + r) * (3*D_) + dq * 4];
        t.x *= 0.125f; t.y *= 0.125f; t.z *= 0.125f; t.w *= 0.125f;
        *(float4*)&S.Q[r][dq * 4] = t;
    }

    auto issueK = [&](int buf, int t) {
        const float* kb = qkv + ((size_t)b * N_ + t * FBN) * (3*D_) + D_ + h * DH_;
        #pragma unroll
        for (int i = 0; i < 8; i++) {
            int v = tid + i * 128;
            int r = v >> 4, dq = v & 15;
            cp16(smem_u32(&S.K[buf][r][dq * 4]), &kb[(size_t)r * (3*D_) + dq * 4]);
        }
    };
    auto issueV = [&](int buf, int t) {
        const float* vb = qkv + ((size_t)b * N_ + t * FBN) * (3*D_) + 2*D_ + h * DH_;
        #pragma unroll
        for (int i = 0; i < 8; i++) {
            int v = tid + i * 128;
            int r = v >> 4, dq = v & 15;
            cp16(smem_u32(&S.V[buf][r][dq * 4]), &vb[(size_t)r * (3*D_) + dq * 4]);
        }
    };

    float mr0 = -1e30f, mr1 = -1e30f, l0 = 0.f, l1 = 0.f;
    float o[8][4];
    #pragma unroll
    for (int nt = 0; nt < 8; nt++)
        #pragma unroll
        for (int c = 0; c < 4; c++) o[nt][c] = 0.f;

    const int qrow = warp * 16 + gid;
    const int NTiles = N_ / FBN;

    issueK(0, 0); cp_commit();
    issueV(0, 0); cp_commit();
    for (int t = 0; t < NTiles; t++) {
        int cur = t & 1;
        cp_wait<1>();                 // K[cur] ready (V may still be in flight)
        __syncthreads();
        if (t + 1 < NTiles) issueK(cur ^ 1, t + 1);
        cp_commit();

        // ---- S = Qs @ K^T ----
        float s[8][4];
        #pragma unroll
        for (int nt = 0; nt < 8; nt++)
            #pragma unroll
            for (int c = 0; c < 4; c++) s[nt][c] = 0.f;

        #pragma unroll
        for (int ks = 0; ks < DH_; ks += 8) {
            float a0 = S.Q[qrow    ][ks + tig];
            float a1 = S.Q[qrow + 8][ks + tig];
            float a2 = S.Q[qrow    ][ks + tig + 4];
            float a3 = S.Q[qrow + 8][ks + tig + 4];
            #pragma unroll
            for (int nt = 0; nt < 8; nt++) {
                float b0 = S.K[cur][nt * 8 + gid][ks + tig];
                float b1 = S.K[cur][nt * 8 + gid][ks + tig + 4];
                mma_tf32(s[nt][0], s[nt][1], s[nt][2], s[nt][3],
                         a0, a1, a2, a3, b0, b1);
            }
        }

        // ---- online softmax update ----
        float rm0 = -1e30f, rm1 = -1e30f;
        #pragma unroll
        for (int nt = 0; nt < 8; nt++) {
            rm0 = fmaxf(rm0, fmaxf(s[nt][0], s[nt][1]));
            rm1 = fmaxf(rm1, fmaxf(s[nt][2], s[nt][3]));
        }
        rm0 = fmaxf(rm0, __shfl_xor_sync(0xffffffff, rm0, 1));
        rm0 = fmaxf(rm0, __shfl_xor_sync(0xffffffff, rm0, 2));
        rm1 = fmaxf(rm1, __shfl_xor_sync(0xffffffff, rm1, 1));
        rm1 = fmaxf(rm1, __shfl_xor_sync(0xffffffff, rm1, 2));

        float mn0 = fmaxf(mr0, rm0), mn1 = fmaxf(mr1, rm1);
        float sc0 = __expf(mr0 - mn0), sc1 = __expf(mr1 - mn1);
        mr0 = mn0; mr1 = mn1;

        float rs0 = 0.f, rs1 = 0.f;
        #pragma unroll
        for (int nt = 0; nt < 8; nt++) {
            s[nt][0] = __expf(s[nt][0] - mn0);
            s[nt][1] = __expf(s[nt][1] - mn0);
            s[nt][2] = __expf(s[nt][2] - mn1);
            s[nt][3] = __expf(s[nt][3] - mn1);
            rs0 += s[nt][0] + s[nt][1];
            rs1 += s[nt][2] + s[nt][3];
        }
        rs0 += __shfl_xor_sync(0xffffffff, rs0, 1);
        rs0 += __shfl_xor_sync(0xffffffff, rs0, 2);
        rs1 += __shfl_xor_sync(0xffffffff, rs1, 1);
        rs1 += __shfl_xor_sync(0xffffffff, rs1, 2);
        l0 = l0 * sc0 + rs0;
        l1 = l1 * sc1 + rs1;

        #pragma unroll
        for (int nt = 0; nt < 8; nt++) {
            o[nt][0] *= sc0; o[nt][1] *= sc0;
            o[nt][2] *= sc1; o[nt][3] *= sc1;
        }

        cp_wait<1>();                 // V[cur] ready (next K may be in flight)
        __syncthreads();
        if (t + 1 < NTiles) issueV(cur ^ 1, t + 1);
        cp_commit();

        // ---- stage P, O += P @ V ----
        #pragma unroll
        for (int nt = 0; nt < 8; nt++) {
            S.P[warp][gid    ][nt * 8 + tig * 2    ] = s[nt][0];
            S.P[warp][gid    ][nt * 8 + tig * 2 + 1] = s[nt][1];
            S.P[warp][gid + 8][nt * 8 + tig * 2    ] = s[nt][2];
            S.P[warp][gid + 8][nt * 8 + tig * 2 + 1] = s[nt][3];
        }
        __syncwarp();

        #pragma unroll
        for (int ks = 0; ks < FBN; ks += 8) {
            float a0 = S.P[warp][gid    ][ks + tig];
            float a1 = S.P[warp][gid + 8][ks + tig];
            float a2 = S.P[warp][gid    ][ks + tig + 4];
            float a3 = S.P[warp][gid + 8][ks + tig + 4];
            #pragma unroll
            for (int nt = 0; nt < 8; nt++) {
                float b0 = S.V[cur][ks + tig    ][nt * 8 + gid];
                float b1 = S.V[cur][ks + tig + 4][nt * 8 + gid];
                mma_tf32(o[nt][0], o[nt][1], o[nt][2], o[nt][3],
                         a0, a1, a2, a3, b0, b1);
            }
        }
        __syncwarp();
    }

    float inv0 = 1.f / l0, inv1 = 1.f / l1;
    int r0 = m0 + qrow;
    float* ob0 = Og + ((size_t)b * N_ + r0    ) * D_ + h * DH_;
    float* ob1 = Og + ((size_t)b * N_ + r0 + 8) * D_ + h * DH_;
    #pragma unroll
    for (int nt = 0; nt < 8; nt++) {
        int col = nt * 8 + tig * 2;
        *(float2*)&ob0[col] = make_float2(o[nt][0] * inv0, o[nt][1] * inv0);
        *(float2*)&ob1[col] = make_float2(o[nt][2] * inv1, o[nt][3] * inv1);
    }
}

// ---------------- dense tensor-core GEMM v6 (tf32, multi-stage cp.async) -----
// C = A @ B (+bias) (+gelu) (+=C if ADD). Dynamic smem ring of STAGES buffers;
// one __syncthreads per K-step (ring depth >= 3 makes overwrite safe).
template<int BM, int BN, int WSM, int WSN, int ACT, int STAGES, int ADD>
__global__ __launch_bounds__(WSM*WSN*32)
void gemm6_k(const float* __restrict__ A, int lda,
             const float* __restrict__ Bm, int ldb,
             float* __restrict__ C, int ldc,
             const float* __restrict__ bias, int K)
{
    constexpr int BK = 16;
    constexpr int NT = WSM * WSN * 32;
    constexpr int WM = BM / WSM, WN = BN / WSN;
    constexpr int MT = WM / 16, NTL = WN / 8;
    constexpr int SA = BK + 4;
    constexpr int SB = BN + 8;
    constexpr int LA = BM * BK / (4 * NT);
    constexpr int LB = BN * BK / (4 * NT);

    extern __shared__ float smem[];
    float (*As)[BM][SA] = reinterpret_cast<float(*)[BM][SA]>(smem);
    float (*Bs)[BK][SB] = reinterpret_cast<float(*)[BK][SB]>(smem + STAGES * BM * SA);

    const int m0 = blockIdx.y * BM;
    const int n0 = blockIdx.x * BN;
    const int tid   = threadIdx.x;
    const int warp  = tid >> 5;
    const int lane  = tid & 31;
    const int gid   = lane >> 2;
    const int tig   = lane & 3;
    const int warpM = warp / WSN;
    const int warpN = warp % WSN;

    auto issue = [&](int buf, int k0) {
        #pragma unroll
        for (int i = 0; i < LA; i++) {
            int v = tid + i * NT;
            int m = v >> 2, kq = v & 3;
            cp16(smem_u32(&As[buf][m][kq * 4]),
                 &A[(size_t)(m0 + m) * lda + k0 + kq * 4]);
        }
        #pragma unroll
        for (int i = 0; i < LB; i++) {
            int v = tid + i * NT;
            int nq = v % (BN / 4), k = v / (BN / 4);
            cp16(smem_u32(&Bs[buf][k][nq * 4]),
                 &Bm[(size_t)(k0 + k) * ldb + n0 + nq * 4]);
        }
    };

    float acc[MT][NTL][4];
    #pragma unroll
    for (int i = 0; i < MT; i++)
        #pragma unroll
        for (int j = 0; j < NTL; j++)
            #pragma unroll
            for (int c = 0; c < 4; c++) acc[i][j][c] = 0.f;

    const int NI = K / BK;
    #pragma unroll
    for (int s = 0; s < STAGES - 1; s++) { issue(s, s * BK); cp_commit(); }

    int cur = 0;
    for (int i = 0; i < NI; i++) {
        cp_wait<STAGES - 2>();
        __syncthreads();
        int nx = i + STAGES - 1;
        if (nx < NI) issue(nx % STAGES, nx * BK);
        cp_commit();

        #pragma unroll
        for (int ks = 0; ks < BK; ks += 8) {
            float af[MT][4], bf[NTL][2];
            #pragma unroll
            for (int mt = 0; mt < MT; mt++) {
                int rb0 = warpM * WM + mt * 16;
                af[mt][0] = As[cur][rb0 + gid    ][ks + tig];
                af[mt][1] = As[cur][rb0 + gid + 8][ks + tig];
                af[mt][2] = As[cur][rb0 + gid    ][ks + tig + 4];
                af[mt][3] = As[cur][rb0 + gid + 8][ks + tig + 4];
            }
            #pragma unroll
            for (int nt = 0; nt < NTL; nt++) {
                int cb0 = warpN * WN + nt * 8;
                bf[nt][0] = Bs[cur][ks + tig    ][cb0 + gid];
                bf[nt][1] = Bs[cur][ks + tig + 4][cb0 + gid];
            }
            #pragma unroll
            for (int mt = 0; mt < MT; mt++)
                #pragma unroll
                for (int nt = 0; nt < NTL; nt++)
                    mma_tf32(acc[mt][nt][0], acc[mt][nt][1],
                             acc[mt][nt][2], acc[mt][nt][3],
                             af[mt][0], af[mt][1], af[mt][2], af[mt][3],
                             bf[nt][0], bf[nt][1]);
        }
        cur++; if (cur == STAGES) cur = 0;
    }

    #pragma unroll
    for (int mt = 0; mt < MT; mt++) {
        int row = m0 + warpM * WM + mt * 16 + gid;
        #pragma unroll
        for (int nt = 0; nt < NTL; nt++) {
            int col = n0 + warpN * WN + nt * 8 + tig * 2;
            float v0 = acc[mt][nt][0];
            float v1 = acc[mt][nt][1];
            float v2 = acc[mt][nt][2];
            float v3 = acc[mt][nt][3];
            if (bias) {
                float b0v = bias[col], b1v = bias[col + 1];
                v0 += b0v; v1 += b1v; v2 += b0v; v3 += b1v;
            }
            if (ACT == 1) {
                v0 = gelu_exact(v0); v1 = gelu_exact(v1);
                v2 = gelu_exact(v2); v3 = gelu_exact(v3);
            }
            if (ADD) {
                float2 p0 = *(float2*)&C[(size_t)row * ldc + col];
                float2 p1 = *(float2*)&C[(size_t)(row + 8) * ldc + col];
                v0 += p0.x; v1 += p0.y; v2 += p1.x; v3 += p1.y;
            }
            *(float2*)&C[(size_t)row * ldc + col]       = make_float2(v0, v1);
            *(float2*)&C[(size_t)(row + 8) * ldc + col] = make_float2(v2, v3);
        }
    }
}

constexpr int gemm6_smem(int BM, int BN, int S) {
    return (S * BM * 20 + S * 16 * (BN + 8)) * 4;
}

// ---------------- fused copy + layernorm (layer 0 entry) --------------------
__global__ void copy_ln_k(const float* __restrict__ xin, float* __restrict__ X,
                          const float* __restrict__ g, const float* __restrict__ b,
                          float* __restrict__ out)
{
    int row = blockIdx.x, tid = threadIdx.x;
    __shared__ float s[256];
    float v = xin[(size_t)row * D_ + tid];
    X[(size_t)row * D_ + tid] = v;
    s[tid] = v; __syncthreads();
    for (int st = 128; st > 0; st >>= 1) { if (tid < st) s[tid] += s[tid + st]; __syncthreads(); }
    float mu = s[0] * (1.f / D_);
    __syncthreads();
    float d = v - mu;
    s[tid] = d * d; __syncthreads();
    for (int st = 128; st > 0; st >>= 1) { if (tid < st) s[tid] += s[tid + st]; __syncthreads(); }
    float var = s[0] * (1.f / D_);
    out[(size_t)row * D_ + tid] = d * rsqrtf(var + EPS_) * g[tid] + b[tid];
}

// ---------------- fused scale + layernorm -----------------------------------
__global__ void scale_ln_k(float* __restrict__ X, const float* __restrict__ gate,
                           const float* __restrict__ g, const float* __restrict__ b,
                           float* __restrict__ out)
{
    int row = blockIdx.x, tid = threadIdx.x;
    int bb = row >> 10;
    __shared__ float s[256];
    float v = X[(size_t)row * D_ + tid] * gate[bb * D_ + tid];
    X[(size_t)row * D_ + tid] = v;
    s[tid] = v; __syncthreads();
    for (int st = 128; st > 0; st >>= 1) { if (tid < st) s[tid] += s[tid + st]; __syncthreads(); }
    float mu = s[0] * (1.f / D_);
    __syncthreads();
    float d = v - mu;
    s[tid] = d * d; __syncthreads();
    for (int st = 128; st > 0; st >>= 1) { if (tid < st) s[tid] += s[tid + st]; __syncthreads(); }
    float var = s[0] * (1.f / D_);
    out[(size_t)row * D_ + tid] = d * rsqrtf(var + EPS_) * g[tid] + b[tid];
}

// ---------------- column-sum partials (read-only; add fused into GEMM) -------
__global__ void colsum_k(const float* __restrict__ X, float* __restrict__ meanp)
{
    int b  = blockIdx.x >> 3;
    int ch = blockIdx.x & 7;
    int d  = threadIdx.x;
    size_t base = ((size_t)b * N_ + ch * 128) * D_ + d;
    float acc = 0.f;
    #pragma unroll 8
    for (int r = 0; r < 128; r++) acc += X[base + (size_t)r * D_];
    meanp[((size_t)b * 8 + ch) * D_ + d] = acc;
}

// SE gate: s = sigmoid(relu(mean @ w1) @ w2); one block per batch
__global__ void gate_k(const float* __restrict__ meanp, const float* __restrict__ w1,
                       const float* __restrict__ w2, float* __restrict__ gatebuf)
{
    int b = blockIdx.x, tid = threadIdx.x;
    __shared__ float m[D_];
    __shared__ float t[D_ / 4];
    float acc0 = 0.f;
    #pragma unroll
    for (int c = 0; c < 8; c++) acc0 += meanp[((size_t)b * 8 + c) * D_ + tid];
    m[tid] = acc0 * (1.f / N_);
    __syncthreads();
    if (tid < D_ / 4) {
        float acc = 0.f;
        #pragma unroll 8
        for (int d = 0; d < D_; d++) acc += m[d] * w1[d * (D_ / 4) + tid];
        t[tid] = fmaxf(acc, 0.f);
    }
    __syncthreads();
    float acc = 0.f;
    #pragma unroll 8
    for (int j = 0; j < D_ / 4; j++) acc += t[j] * w2[j * D_ + tid];
    gatebuf[b * D_ + tid] = 1.f / (1.f + expf(-acc));
}

__global__ void scale_k(float* __restrict__ x, const float* __restrict__ gate)
{
    int idx = blockIdx.x * 256 + threadIdx.x;
    int d = idx & (D_ - 1);
    int b = idx / (N_ * D_);
    x[idx] *= gate[b * D_ + d];
}

// depthwise 1x3 conv over tokens + center-tap conv + BN(eval) + exact gelu
__global__ void conv_k(const float* __restrict__ y, const float* __restrict__ wh,
                       const float* __restrict__ bh, const float* __restrict__ wv,
                       const float* __restrict__ bv, const float* __restrict__ bng,
                       const float* __restrict__ bnb, const float* __restrict__ bnm,
                       const float* __restrict__ bnv, float* __restrict__ out)
{
    int idx = blockIdx.x * 256 + threadIdx.x;
    int m = idx & (M_ - 1);
    int n = (idx / M_) & (N_ - 1);
    float y0 = y[idx];
    float ym = (n > 0)      ? y[idx - M_] : 0.f;
    float yp = (n < N_ - 1) ? y[idx + M_] : 0.f;
    float ch = wh[m * 3 + 0] * ym + wh[m * 3 + 1] * y0 + wh[m * 3 + 2] * yp + bh[m];
    float cv = wv[m * 3 + 1] * y0 + bv[m];
    float zz = ch + cv;
    zz = (zz - bnm[m]) * rsqrtf(bnv[m] + EPS_) * bng[m] + bnb[m];
    out[idx] = gelu_exact(zz);
}

// ---------------- driver -----------------------------------------------------
extern "C" void kernel_launch(void* const* d_in, const int* in_sizes, int n_in,
                              void* d_out, int out_size)
{
    const float* x_in  = (const float*)d_in[0];
    const float* ln1_g = (const float*)d_in[1];
    const float* ln1_b = (const float*)d_in[2];
    const float* w_qkv = (const float*)d_in[3];
    const float* w_out = (const float*)d_in[4];
    const float* b_out = (const float*)d_in[5];
    const float* ln2_g = (const float*)d_in[6];
    const float* ln2_b = (const float*)d_in[7];
    const float* w_fc1 = (const float*)d_in[8];
    const float* b_fc1 = (const float*)d_in[9];
    const float* wh    = (const float*)d_in[10];
    const float* bh    = (const float*)d_in[11];
    const float* wv    = (const float*)d_in[12];
    const float* bv    = (const float*)d_in[13];
    const float* bn_g  = (const float*)d_in[14];
    const float* bn_b  = (const float*)d_in[15];
    const float* bn_m  = (const float*)d_in[16];
    const float* bn_v  = (const float*)d_in[17];
    const float* w_fc2 = (const float*)d_in[18];
    const float* b_fc2 = (const float*)d_in[19];
    const float* ls_w1 = (const float*)d_in[20];
    const float* ls_w2 = (const float*)d_in[21];

    float *ph, *pqkv, *po, *pt1, *pt2, *pmeanp, *pgate;
    cudaGetSymbolAddress((void**)&ph,     g_h);
    cudaGetSymbolAddress((void**)&pqkv,   g_qkv);
    cudaGetSymbolAddress((void**)&po,     g_o);
    cudaGetSymbolAddress((void**)&pt1,    g_t1);
    cudaGetSymbolAddress((void**)&pt2,    g_t2);
    cudaGetSymbolAddress((void**)&pmeanp, g_meanp);
    cudaGetSymbolAddress((void**)&pgate,  g_gate);

    constexpr int SM_BIG  = gemm6_smem(128, 128, 3);   // 56832
    constexpr int SM_THIN = gemm6_smem(64, 64, 4);     // 38912

    cudaFuncSetAttribute(flash_k, cudaFuncAttributeMaxDynamicSharedMemorySize,
                         FLASH_SMEM_BYTES);
    cudaFuncSetAttribute(gemm6_k<128,128,2,4,0,3,0>,
                         cudaFuncAttributeMaxDynamicSharedMemorySize, SM_BIG);
    cudaFuncSetAttribute(gemm6_k<128,128,2,4,1,3,0>,
                         cudaFuncAttributeMaxDynamicSharedMemorySize, SM_BIG);
    cudaFuncSetAttribute(gemm6_k<64,64,2,2,0,4,1>,
                         cudaFuncAttributeMaxDynamicSharedMemorySize, SM_THIN);

    float* X = (float*)d_out;
    const int ROWS = B_ * N_;   // 8192

    for (int l = 0; l < 2; l++) {
        const float* w_qkv_l = w_qkv + (size_t)l * D_ * 3 * D_;
        const float* w_out_l = w_out + (size_t)l * D_ * D_;
        const float* b_out_l = b_out + (size_t)l * D_;
        const float* w_fc1_l = w_fc1 + (size_t)l * D_ * M_;
        const float* b_fc1_l = b_fc1 + (size_t)l * M_;
        const float* w_fc2_l = w_fc2 + (size_t)l * M_ * D_;
        const float* b_fc2_l = b_fc2 + (size_t)l * D_;
        const float* w1_l    = ls_w1 + (size_t)l * D_ * (D_/4);
        const float* w2_l    = ls_w2 + (size_t)l * (D_/4) * D_;

        // --- MHSA ---  (h = LN1(X); layer 0 fuses the initial copy)
        if (l == 0)
            copy_ln_k<<<ROWS, 256>>>(x_in, X, ln1_g, ln1_b, ph);

        // qkv = h @ w_qkv
        gemm6_k<128,128,2,4,0,3,0><<<dim3((3*D_)/128, ROWS/128, 1), 256, SM_BIG>>>(
            ph, D_, w_qkv_l, 3*D_, pqkv, 3*D_, nullptr, D_);

        // fused attention
        flash_k<<<dim3(1, N_/FBM, B_*H_), 128, FLASH_SMEM_BYTES>>>(pqkv, po);

        // X += o @ w_out + b_out   (residual add fused into epilogue)
        gemm6_k<64,64,2,2,0,4,1><<<dim3(D_/64, ROWS/64, 1), 128, SM_THIN>>>(
            po, D_, w_out_l, D_, X, D_, b_out_l, D_);

        // lsrc #1
        colsum_k<<<B_ * 8, 256>>>(X, pmeanp);
        gate_k<<<B_, 256>>>(pmeanp, w1_l, w2_l, pgate);
        scale_ln_k<<<ROWS, 256>>>(X, pgate, ln2_g + l * D_, ln2_b + l * D_, ph);

        // --- MLP ---
        gemm6_k<128,128,2,4,1,3,0><<<dim3(M_/128, ROWS/128, 1), 256, SM_BIG>>>(
            ph, D_, w_fc1_l, M_, pt1, M_, b_fc1_l, D_);

        conv_k<<<(B_*N_*M_)/256, 256>>>(
            pt1, wh + (size_t)l*M_*3, bh + (size_t)l*M_,
            wv + (size_t)l*M_*3, bv + (size_t)l*M_,
            bn_g + (size_t)l*M_, bn_b + (size_t)l*M_,
            bn_m + (size_t)l*M_, bn_v + (size_t)l*M_, pt2);

        // X += t2 @ w_fc2 + b_fc2
        gemm6_k<64,64,2,2,0,4,1><<<dim3(D_/64, ROWS/64, 1), 128, SM_THIN>>>(
            pt2, M_, w_fc2_l, D_, X, D_, b_fc2_l, M_);

        // lsrc #2
        colsum_k<<<B_ * 8, 256>>>(X, pmeanp);
        gate_k<<<B_, 256>>>(pmeanp, w1_l, w2_l, pgate);
        if (l + 1 < 2)
            scale_ln_k<<<ROWS, 256>>>(X, pgate, ln1_g + (l+1) * D_, ln1_b + (l+1) * D_, ph);
        else
            scale_k<<<(B_*N_*D_)/256, 256>>>(X, pgate);
    }
}

// round 9
// speedup vs baseline: 1.1857x; 1.1110x over previous
#include <cuda_runtime.h>
#include <math.h>
#include <stdint.h>

#define B_  8
#define N_  1024
#define D_  256
#define H_  4
#define DH_ 64
#define M_  512
#define EPS_ 1e-5f

// ---------------- scratch (device globals; no allocations allowed) ----------
__device__ float g_h[B_*N_*D_];                 // LN output
__device__ float g_qkv[B_*N_*3*D_];             // qkv
__device__ float g_o[B_*N_*D_];                 // attn out
__device__ float g_t1[B_*N_*M_];                // fc1/gelu out
__device__ float g_t2[B_*N_*M_];                // conv/bn/gelu out
__device__ float g_meanp2[128*256];             // colsum partials per row-tile
__device__ float g_gate[B_*D_];

__device__ __forceinline__ float gelu_exact(float v) {
    return 0.5f * v * (1.f + erff(v * 0.70710678118654752f));
}

__device__ __forceinline__ void mma_tf32(float& c0, float& c1, float& c2, float& c3,
                                         float a0, float a1, float a2, float a3,
                                         float b0, float b1)
{
    asm volatile(
        "mma.sync.aligned.m16n8k8.row.col.f32.tf32.tf32.f32 "
        "{%0,%1,%2,%3},{%4,%5,%6,%7},{%8,%9},{%0,%1,%2,%3};"
        : "+f"(c0), "+f"(c1), "+f"(c2), "+f"(c3)
        : "r"(__float_as_uint(a0)), "r"(__float_as_uint(a1)),
          "r"(__float_as_uint(a2)), "r"(__float_as_uint(a3)),
          "r"(__float_as_uint(b0)), "r"(__float_as_uint(b1)));
}

__device__ __forceinline__ void cp16(uint32_t dst, const void* src) {
    asm volatile("cp.async.cg.shared.global [%0], [%1], 16;" :: "r"(dst), "l"(src));
}
__device__ __forceinline__ void cp_commit() {
    asm volatile("cp.async.commit_group;" ::: "memory");
}
template<int N>
__device__ __forceinline__ void cp_wait() {
    asm volatile("cp.async.wait_group %0;" :: "n"(N) : "memory");
}
__device__ __forceinline__ uint32_t smem_u32(const void* p) {
    return (uint32_t)__cvta_generic_to_shared(p);
}

// ---------------- flash attention (split K/V waits) --------------------------
#define FBM 64
#define FBN 64

struct FlashSmem {
    float Q[FBM][68];
    float K[2][FBN][68];
    float V[2][FBN][72];
    float P[4][16][68];
};
#define FLASH_SMEM_BYTES ((int)sizeof(FlashSmem))

__global__ __launch_bounds__(128)
void flash_k(const float* __restrict__ qkv, float* __restrict__ Og)
{
    extern __shared__ float smem_raw[];
    FlashSmem& S = *(FlashSmem*)smem_raw;

    const int bh = blockIdx.z;
    const int b = bh >> 2, h = bh & 3;
    const int m0 = blockIdx.y * FBM;
    const int tid  = threadIdx.x;
    const int warp = tid >> 5, lane = tid & 31;
    const int gid  = lane >> 2, tig = lane & 3;

    const float* qb = qkv + ((size_t)b * N_) * (3*D_) + h * DH_;

    #pragma unroll
    for (int i = 0; i < 8; i++) {
        int v = tid + i * 128;
        int r = v >> 4, dq = v & 15;
        float4 t = *(const float4*)&qb[(size_t)(m0 + r) * (3*D_) + dq * 4];
        t.x *= 0.125f; t.y *= 0.125f; t.z *= 0.125f; t.w *= 0.125f;
        *(float4*)&S.Q[r][dq * 4] = t;
    }

    auto issueK = [&](int buf, int t) {
        const float* kb = qkv + ((size_t)b * N_ + t * FBN) * (3*D_) + D_ + h * DH_;
        #pragma unroll
        for (int i = 0; i < 8; i++) {
            int v = tid + i * 128;
            int r = v >> 4, dq = v & 15;
            cp16(smem_u32(&S.K[buf][r][dq * 4]), &kb[(size_t)r * (3*D_) + dq * 4]);
        }
    };
    auto issueV = [&](int buf, int t) {
        const float* vb = qkv + ((size_t)b * N_ + t * FBN) * (3*D_) + 2*D_ + h * DH_;
        #pragma unroll
        for (int i = 0; i < 8; i++) {
            int v = tid + i * 128;
            int r = v >> 4, dq = v & 15;
            cp16(smem_u32(&S.V[buf][r][dq * 4]), &vb[(size_t)r * (3*D_) + dq * 4]);
        }
    };

    float mr0 = -1e30f, mr1 = -1e30f, l0 = 0.f, l1 = 0.f;
    float o[8][4];
    #pragma unroll
    for (int nt = 0; nt < 8; nt++)
        #pragma unroll
        for (int c = 0; c < 4; c++) o[nt][c] = 0.f;

    const int qrow = warp * 16 + gid;
    const int NTiles = N_ / FBN;

    issueK(0, 0); cp_commit();
    issueV(0, 0); cp_commit();
    for (int t = 0; t < NTiles; t++) {
        int cur = t & 1;
        cp_wait<1>();
        __syncthreads();
        if (t + 1 < NTiles) issueK(cur ^ 1, t + 1);
        cp_commit();

        float s[8][4];
        #pragma unroll
        for (int nt = 0; nt < 8; nt++)
            #pragma unroll
            for (int c = 0; c < 4; c++) s[nt][c] = 0.f;

        #pragma unroll
        for (int ks = 0; ks < DH_; ks += 8) {
            float a0 = S.Q[qrow    ][ks + tig];
            float a1 = S.Q[qrow + 8][ks + tig];
            float a2 = S.Q[qrow    ][ks + tig + 4];
            float a3 = S.Q[qrow + 8][ks + tig + 4];
            #pragma unroll
            for (int nt = 0; nt < 8; nt++) {
                float b0 = S.K[cur][nt * 8 + gid][ks + tig];
                float b1 = S.K[cur][nt * 8 + gid][ks + tig + 4];
                mma_tf32(s[nt][0], s[nt][1], s[nt][2], s[nt][3],
                         a0, a1, a2, a3, b0, b1);
            }
        }

        float rm0 = -1e30f, rm1 = -1e30f;
        #pragma unroll
        for (int nt = 0; nt < 8; nt++) {
            rm0 = fmaxf(rm0, fmaxf(s[nt][0], s[nt][1]));
            rm1 = fmaxf(rm1, fmaxf(s[nt][2], s[nt][3]));
        }
        rm0 = fmaxf(rm0, __shfl_xor_sync(0xffffffff, rm0, 1));
        rm0 = fmaxf(rm0, __shfl_xor_sync(0xffffffff, rm0, 2));
        rm1 = fmaxf(rm1, __shfl_xor_sync(0xffffffff, rm1, 1));
        rm1 = fmaxf(rm1, __shfl_xor_sync(0xffffffff, rm1, 2));

        float mn0 = fmaxf(mr0, rm0), mn1 = fmaxf(mr1, rm1);
        float sc0 = __expf(mr0 - mn0), sc1 = __expf(mr1 - mn1);
        mr0 = mn0; mr1 = mn1;

        float rs0 = 0.f, rs1 = 0.f;
        #pragma unroll
        for (int nt = 0; nt < 8; nt++) {
            s[nt][0] = __expf(s[nt][0] - mn0);
            s[nt][1] = __expf(s[nt][1] - mn0);
            s[nt][2] = __expf(s[nt][2] - mn1);
            s[nt][3] = __expf(s[nt][3] - mn1);
            rs0 += s[nt][0] + s[nt][1];
            rs1 += s[nt][2] + s[nt][3];
        }
        rs0 += __shfl_xor_sync(0xffffffff, rs0, 1);
        rs0 += __shfl_xor_sync(0xffffffff, rs0, 2);
        rs1 += __shfl_xor_sync(0xffffffff, rs1, 1);
        rs1 += __shfl_xor_sync(0xffffffff, rs1, 2);
        l0 = l0 * sc0 + rs0;
        l1 = l1 * sc1 + rs1;

        #pragma unroll
        for (int nt = 0; nt < 8; nt++) {
            o[nt][0] *= sc0; o[nt][1] *= sc0;
            o[nt][2] *= sc1; o[nt][3] *= sc1;
        }

        cp_wait<1>();
        __syncthreads();
        if (t + 1 < NTiles) issueV(cur ^ 1, t + 1);
        cp_commit();

        #pragma unroll
        for (int nt = 0; nt < 8; nt++) {
            S.P[warp][gid    ][nt * 8 + tig * 2    ] = s[nt][0];
            S.P[warp][gid    ][nt * 8 + tig * 2 + 1] = s[nt][1];
            S.P[warp][gid + 8][nt * 8 + tig * 2    ] = s[nt][2];
            S.P[warp][gid + 8][nt * 8 + tig * 2 + 1] = s[nt][3];
        }
        __syncwarp();

        #pragma unroll
        for (int ks = 0; ks < FBN; ks += 8) {
            float a0 = S.P[warp][gid    ][ks + tig];
            float a1 = S.P[warp][gid + 8][ks + tig];
            float a2 = S.P[warp][gid    ][ks + tig + 4];
            float a3 = S.P[warp][gid + 8][ks + tig + 4];
            #pragma unroll
            for (int nt = 0; nt < 8; nt++) {
                float b0 = S.V[cur][ks + tig    ][nt * 8 + gid];
                float b1 = S.V[cur][ks + tig + 4][nt * 8 + gid];
                mma_tf32(o[nt][0], o[nt][1], o[nt][2], o[nt][3],
                         a0, a1, a2, a3, b0, b1);
            }
        }
        __syncwarp();
    }

    float inv0 = 1.f / l0, inv1 = 1.f / l1;
    int r0 = m0 + qrow;
    float* ob0 = Og + ((size_t)b * N_ + r0    ) * D_ + h * DH_;
    float* ob1 = Og + ((size_t)b * N_ + r0 + 8) * D_ + h * DH_;
    #pragma unroll
    for (int nt = 0; nt < 8; nt++) {
        int col = nt * 8 + tig * 2;
        *(float2*)&ob0[col] = make_float2(o[nt][0] * inv0, o[nt][1] * inv0);
        *(float2*)&ob1[col] = make_float2(o[nt][2] * inv1, o[nt][3] * inv1);
    }
}

// ---------------- dense tensor-core GEMM v7 (tf32, multi-stage, param BK) ----
// C = A @ B (+bias) (+gelu) (+=C if ADD) (+column partials if CSUM).
template<int BM, int BN, int BK, int WSM, int WSN, int ACT, int STAGES, int ADD, int CSUM>
__global__ __launch_bounds__(WSM*WSN*32)
void gemm7_k(const float* __restrict__ A, int lda,
             const float* __restrict__ Bm, int ldb,
             float* __restrict__ C, int ldc,
             const float* __restrict__ bias, int K,
             float* __restrict__ meanp2)
{
    constexpr int NT = WSM * WSN * 32;
    constexpr int WM = BM / WSM, WN = BN / WSN;
    constexpr int MT = WM / 16, NTL = WN / 8;
    constexpr int SA = BK + 4;
    constexpr int SB = BN + 8;
    constexpr int LA = BM * BK / (4 * NT);
    constexpr int LB = BN * BK / (4 * NT);
    constexpr int KQ = BK / 4;

    extern __shared__ float smem[];
    float (*As)[BM][SA] = reinterpret_cast<float(*)[BM][SA]>(smem);
    float (*Bs)[BK][SB] = reinterpret_cast<float(*)[BK][SB]>(smem + STAGES * BM * SA);
    __shared__ float cred[WSM][BN];

    const int m0 = blockIdx.y * BM;
    const int n0 = blockIdx.x * BN;
    const int tid   = threadIdx.x;
    const int warp  = tid >> 5;
    const int lane  = tid & 31;
    const int gid   = lane >> 2;
    const int tig   = lane & 3;
    const int warpM = warp / WSN;
    const int warpN = warp % WSN;

    auto issue = [&](int buf, int k0) {
        #pragma unroll
        for (int i = 0; i < LA; i++) {
            int v = tid + i * NT;
            int m = v / KQ, kq = v % KQ;
            cp16(smem_u32(&As[buf][m][kq * 4]),
                 &A[(size_t)(m0 + m) * lda + k0 + kq * 4]);
        }
        #pragma unroll
        for (int i = 0; i < LB; i++) {
            int v = tid + i * NT;
            int nq = v % (BN / 4), k = v / (BN / 4);
            cp16(smem_u32(&Bs[buf][k][nq * 4]),
                 &Bm[(size_t)(k0 + k) * ldb + n0 + nq * 4]);
        }
    };

    float acc[MT][NTL][4];
    #pragma unroll
    for (int i = 0; i < MT; i++)
        #pragma unroll
        for (int j = 0; j < NTL; j++)
            #pragma unroll
            for (int c = 0; c < 4; c++) acc[i][j][c] = 0.f;

    const int NI = K / BK;
    #pragma unroll
    for (int s = 0; s < STAGES - 1; s++) { issue(s, s * BK); cp_commit(); }

    int cur = 0;
    for (int i = 0; i < NI; i++) {
        cp_wait<STAGES - 2>();
        __syncthreads();
        int nx = i + STAGES - 1;
        if (nx < NI) issue(nx % STAGES, nx * BK);
        cp_commit();

        #pragma unroll
        for (int ks = 0; ks < BK; ks += 8) {
            float af[MT][4], bf[NTL][2];
            #pragma unroll
            for (int mt = 0; mt < MT; mt++) {
                int rb0 = warpM * WM + mt * 16;
                af[mt][0] = As[cur][rb0 + gid    ][ks + tig];
                af[mt][1] = As[cur][rb0 + gid + 8][ks + tig];
                af[mt][2] = As[cur][rb0 + gid    ][ks + tig + 4];
                af[mt][3] = As[cur][rb0 + gid + 8][ks + tig + 4];
            }
            #pragma unroll
            for (int nt = 0; nt < NTL; nt++) {
                int cb0 = warpN * WN + nt * 8;
                bf[nt][0] = Bs[cur][ks + tig    ][cb0 + gid];
                bf[nt][1] = Bs[cur][ks + tig + 4][cb0 + gid];
            }
            #pragma unroll
            for (int mt = 0; mt < MT; mt++)
                #pragma unroll
                for (int nt = 0; nt < NTL; nt++)
                    mma_tf32(acc[mt][nt][0], acc[mt][nt][1],
                             acc[mt][nt][2], acc[mt][nt][3],
                             af[mt][0], af[mt][1], af[mt][2], af[mt][3],
                             bf[nt][0], bf[nt][1]);
        }
        cur++; if (cur == STAGES) cur = 0;
    }

    float colacc[NTL][2];
    #pragma unroll
    for (int nt = 0; nt < NTL; nt++) { colacc[nt][0] = 0.f; colacc[nt][1] = 0.f; }

    #pragma unroll
    for (int mt = 0; mt < MT; mt++) {
        int row = m0 + warpM * WM + mt * 16 + gid;
        #pragma unroll
        for (int nt = 0; nt < NTL; nt++) {
            int col = n0 + warpN * WN + nt * 8 + tig * 2;
            float v0 = acc[mt][nt][0];
            float v1 = acc[mt][nt][1];
            float v2 = acc[mt][nt][2];
            float v3 = acc[mt][nt][3];
            if (bias) {
                float b0v = bias[col], b1v = bias[col + 1];
                v0 += b0v; v1 += b1v; v2 += b0v; v3 += b1v;
            }
            if (ACT == 1) {
                v0 = gelu_exact(v0); v1 = gelu_exact(v1);
                v2 = gelu_exact(v2); v3 = gelu_exact(v3);
            }
            if (ADD) {
                float2 p0 = *(float2*)&C[(size_t)row * ldc + col];
                float2 p1 = *(float2*)&C[(size_t)(row + 8) * ldc + col];
                v0 += p0.x; v1 += p0.y; v2 += p1.x; v3 += p1.y;
            }
            if (CSUM) {
                colacc[nt][0] += v0 + v2;
                colacc[nt][1] += v1 + v3;
            }
            *(float2*)&C[(size_t)row * ldc + col]       = make_float2(v0, v1);
            *(float2*)&C[(size_t)(row + 8) * ldc + col] = make_float2(v2, v3);
        }
    }

    if (CSUM) {
        #pragma unroll
        for (int nt = 0; nt < NTL; nt++) {
            #pragma unroll
            for (int c = 0; c < 2; c++) {
                float s = colacc[nt][c];
                s += __shfl_xor_sync(0xffffffff, s, 4);
                s += __shfl_xor_sync(0xffffffff, s, 8);
                s += __shfl_xor_sync(0xffffffff, s, 16);
                if (gid == 0)
                    cred[warpM][warpN * WN + nt * 8 + tig * 2 + c] = s;
            }
        }
        __syncthreads();
        if (tid < BN) {
            float s = 0.f;
            #pragma unroll
            for (int wm = 0; wm < WSM; wm++) s += cred[wm][tid];
            meanp2[(size_t)blockIdx.y * 256 + n0 + tid] = s;
        }
    }
}

constexpr int gemm7_smem(int BM, int BN, int BK, int S) {
    return (S * BM * (BK + 4) + S * BK * (BN + 8)) * 4;
}

// ---------------- fused copy + layernorm (single-sync E[x^2] reduction) ------
__global__ void copy_ln_k(const float* __restrict__ xin, float* __restrict__ X,
                          const float* __restrict__ g, const float* __restrict__ b,
                          float* __restrict__ out)
{
    int row = blockIdx.x, tid = threadIdx.x;
    int warp = tid >> 5, lane = tid & 31;
    __shared__ float r1[8], r2[8];
    float v = xin[(size_t)row * D_ + tid];
    X[(size_t)row * D_ + tid] = v;
    float s = v, s2 = v * v;
    #pragma unroll
    for (int m = 16; m > 0; m >>= 1) {
        s  += __shfl_xor_sync(0xffffffff, s, m);
        s2 += __shfl_xor_sync(0xffffffff, s2, m);
    }
    if (lane == 0) { r1[warp] = s; r2[warp] = s2; }
    __syncthreads();
    float ts = 0.f, ts2 = 0.f;
    #pragma unroll
    for (int w = 0; w < 8; w++) { ts += r1[w]; ts2 += r2[w]; }
    float mu = ts * (1.f / D_);
    float var = ts2 * (1.f / D_) - mu * mu;
    out[(size_t)row * D_ + tid] = (v - mu) * rsqrtf(var + EPS_) * g[tid] + b[tid];
}

// ---------------- fused scale + layernorm ------------------------------------
__global__ void scale_ln_k(float* __restrict__ X, const float* __restrict__ gate,
                           const float* __restrict__ g, const float* __restrict__ b,
                           float* __restrict__ out)
{
    int row = blockIdx.x, tid = threadIdx.x;
    int bb = row >> 10;
    int warp = tid >> 5, lane = tid & 31;
    __shared__ float r1[8], r2[8];
    float v = X[(size_t)row * D_ + tid] * gate[bb * D_ + tid];
    X[(size_t)row * D_ + tid] = v;
    float s = v, s2 = v * v;
    #pragma unroll
    for (int m = 16; m > 0; m >>= 1) {
        s  += __shfl_xor_sync(0xffffffff, s, m);
        s2 += __shfl_xor_sync(0xffffffff, s2, m);
    }
    if (lane == 0) { r1[warp] = s; r2[warp] = s2; }
    __syncthreads();
    float ts = 0.f, ts2 = 0.f;
    #pragma unroll
    for (int w = 0; w < 8; w++) { ts += r1[w]; ts2 += r2[w]; }
    float mu = ts * (1.f / D_);
    float var = ts2 * (1.f / D_) - mu * mu;
    out[(size_t)row * D_ + tid] = (v - mu) * rsqrtf(var + EPS_) * g[tid] + b[tid];
}

// SE gate: s = sigmoid(relu(mean @ w1) @ w2); one block per batch
__global__ void gate_k(const float* __restrict__ meanp2, const float* __restrict__ w1,
                       const float* __restrict__ w2, float* __restrict__ gatebuf)
{
    int b = blockIdx.x, tid = threadIdx.x;
    __shared__ float m[D_];
    __shared__ float t[D_ / 4];
    float acc0 = 0.f;
    #pragma unroll
    for (int i = 0; i < 16; i++)
        acc0 += meanp2[((size_t)(b * 16 + i)) * 256 + tid];
    m[tid] = acc0 * (1.f / N_);
    __syncthreads();
    if (tid < D_ / 4) {
        float acc = 0.f;
        #pragma unroll 8
        for (int d = 0; d < D_; d++) acc += m[d] * w1[d * (D_ / 4) + tid];
        t[tid] = fmaxf(acc, 0.f);
    }
    __syncthreads();
    float acc = 0.f;
    #pragma unroll 8
    for (int j = 0; j < D_ / 4; j++) acc += t[j] * w2[j * D_ + tid];
    gatebuf[b * D_ + tid] = 1.f / (1.f + expf(-acc));
}

__global__ void scale_k(float4* __restrict__ x, const float* __restrict__ gate)
{
    int idx = blockIdx.x * 256 + threadIdx.x;      // float4 index
    int d4 = idx & (D_ / 4 - 1);
    int b = idx / (N_ * D_ / 4);
    const float4 gv = *(const float4*)&gate[b * D_ + d4 * 4];
    float4 v = x[idx];
    v.x *= gv.x; v.y *= gv.y; v.z *= gv.z; v.w *= gv.w;
    x[idx] = v;
}

// depthwise 1x3 conv + center-tap + BN(eval) + exact gelu (float4)
__global__ void conv_k(const float4* __restrict__ y, const float* __restrict__ wh,
                       const float* __restrict__ bh, const float* __restrict__ wv,
                       const float* __restrict__ bv, const float* __restrict__ bng,
                       const float* __restrict__ bnb, const float* __restrict__ bnm,
                       const float* __restrict__ bnv, float4* __restrict__ out)
{
    int idx = blockIdx.x * 256 + threadIdx.x;      // float4 index
    int m4 = idx & (M_ / 4 - 1);
    int n = (idx / (M_ / 4)) & (N_ - 1);
    int m = m4 * 4;
    float4 y0 = y[idx];
    float4 ym = (n > 0)      ? y[idx - M_ / 4] : make_float4(0.f, 0.f, 0.f, 0.f);
    float4 yp = (n < N_ - 1) ? y[idx + M_ / 4] : make_float4(0.f, 0.f, 0.f, 0.f);
    float r[4];
    float y0a[4] = {y0.x, y0.y, y0.z, y0.w};
    float yma[4] = {ym.x, ym.y, ym.z, ym.w};
    float ypa[4] = {yp.x, yp.y, yp.z, yp.w};
    #pragma unroll
    for (int j = 0; j < 4; j++) {
        int mm = m + j;
        float ch = wh[mm * 3 + 0] * yma[j] + wh[mm * 3 + 1] * y0a[j]
                 + wh[mm * 3 + 2] * ypa[j] + bh[mm];
        float cv = wv[mm * 3 + 1] * y0a[j] + bv[mm];
        float zz = ch + cv;
        zz = (zz - bnm[mm]) * rsqrtf(bnv[mm] + EPS_) * bng[mm] + bnb[mm];
        r[j] = gelu_exact(zz);
    }
    out[idx] = make_float4(r[0], r[1], r[2], r[3]);
}

// ---------------- driver -----------------------------------------------------
extern "C" void kernel_launch(void* const* d_in, const int* in_sizes, int n_in,
                              void* d_out, int out_size)
{
    const float* x_in  = (const float*)d_in[0];
    const float* ln1_g = (const float*)d_in[1];
    const float* ln1_b = (const float*)d_in[2];
    const float* w_qkv = (const float*)d_in[3];
    const float* w_out = (const float*)d_in[4];
    const float* b_out = (const float*)d_in[5];
    const float* ln2_g = (const float*)d_in[6];
    const float* ln2_b = (const float*)d_in[7];
    const float* w_fc1 = (const float*)d_in[8];
    const float* b_fc1 = (const float*)d_in[9];
    const float* wh    = (const float*)d_in[10];
    const float* bh    = (const float*)d_in[11];
    const float* wv    = (const float*)d_in[12];
    const float* bv    = (const float*)d_in[13];
    const float* bn_g  = (const float*)d_in[14];
    const float* bn_b  = (const float*)d_in[15];
    const float* bn_m  = (const float*)d_in[16];
    const float* bn_v  = (const float*)d_in[17];
    const float* w_fc2 = (const float*)d_in[18];
    const float* b_fc2 = (const float*)d_in[19];
    const float* ls_w1 = (const float*)d_in[20];
    const float* ls_w2 = (const float*)d_in[21];

    float *ph, *pqkv, *po, *pt1, *pt2, *pmeanp2, *pgate;
    cudaGetSymbolAddress((void**)&ph,      g_h);
    cudaGetSymbolAddress((void**)&pqkv,    g_qkv);
    cudaGetSymbolAddress((void**)&po,      g_o);
    cudaGetSymbolAddress((void**)&pt1,     g_t1);
    cudaGetSymbolAddress((void**)&pt2,     g_t2);
    cudaGetSymbolAddress((void**)&pmeanp2, g_meanp2);
    cudaGetSymbolAddress((void**)&pgate,   g_gate);

    constexpr int SM_BIG  = gemm7_smem(128, 128, 16, 3);   // 56832
    constexpr int SM_THIN = gemm7_smem(64, 64, 32, 3);     // 55296

    cudaFuncSetAttribute(flash_k, cudaFuncAttributeMaxDynamicSharedMemorySize,
                         FLASH_SMEM_BYTES);
    cudaFuncSetAttribute(gemm7_k<128,128,16,2,4,0,3,0,0>,
                         cudaFuncAttributeMaxDynamicSharedMemorySize, SM_BIG);
    cudaFuncSetAttribute(gemm7_k<128,128,16,2,4,1,3,0,0>,
                         cudaFuncAttributeMaxDynamicSharedMemorySize, SM_BIG);
    cudaFuncSetAttribute(gemm7_k<64,64,32,2,2,0,3,1,1>,
                         cudaFuncAttributeMaxDynamicSharedMemorySize, SM_THIN);

    float* X = (float*)d_out;
    const int ROWS = B_ * N_;   // 8192

    for (int l = 0; l < 2; l++) {
        const float* w_qkv_l = w_qkv + (size_t)l * D_ * 3 * D_;
        const float* w_out_l = w_out + (size_t)l * D_ * D_;
        const float* b_out_l = b_out + (size_t)l * D_;
        const float* w_fc1_l = w_fc1 + (size_t)l * D_ * M_;
        const float* b_fc1_l = b_fc1 + (size_t)l * M_;
        const float* w_fc2_l = w_fc2 + (size_t)l * M_ * D_;
        const float* b_fc2_l = b_fc2 + (size_t)l * D_;
        const float* w1_l    = ls_w1 + (size_t)l * D_ * (D_/4);
        const float* w2_l    = ls_w2 + (size_t)l * (D_/4) * D_;

        // --- MHSA ---  (h = LN1(X); layer 0 fuses the initial copy)
        if (l == 0)
            copy_ln_k<<<ROWS, 256>>>(x_in, X, ln1_g, ln1_b, ph);

        // qkv = h @ w_qkv
        gemm7_k<128,128,16,2,4,0,3,0,0><<<dim3((3*D_)/128, ROWS/128, 1), 256, SM_BIG>>>(
            ph, D_, w_qkv_l, 3*D_, pqkv, 3*D_, nullptr, D_, nullptr);

        // fused attention
        flash_k<<<dim3(1, N_/FBM, B_*H_), 128, FLASH_SMEM_BYTES>>>(pqkv, po);

        // X += o @ w_out + b_out  (residual add + colsum fused)
        gemm7_k<64,64,32,2,2,0,3,1,1><<<dim3(D_/64, ROWS/64, 1), 128, SM_THIN>>>(
            po, D_, w_out_l, D_, X, D_, b_out_l, D_, pmeanp2);

        // lsrc #1
        gate_k<<<B_, 256>>>(pmeanp2, w1_l, w2_l, pgate);
        scale_ln_k<<<ROWS, 256>>>(X, pgate, ln2_g + l * D_, ln2_b + l * D_, ph);

        // --- MLP ---
        gemm7_k<128,128,16,2,4,1,3,0,0><<<dim3(M_/128, ROWS/128, 1), 256, SM_BIG>>>(
            ph, D_, w_fc1_l, M_, pt1, M_, b_fc1_l, D_, nullptr);

        conv_k<<<(B_*N_*M_)/1024, 256>>>(
            (const float4*)pt1, wh + (size_t)l*M_*3, bh + (size_t)l*M_,
            wv + (size_t)l*M_*3, bv + (size_t)l*M_,
            bn_g + (size_t)l*M_, bn_b + (size_t)l*M_,
            bn_m + (size_t)l*M_, bn_v + (size_t)l*M_, (float4*)pt2);

        // X += t2 @ w_fc2 + b_fc2  (residual add + colsum fused)
        gemm7_k<64,64,32,2,2,0,3,1,1><<<dim3(D_/64, ROWS/64, 1), 128, SM_THIN>>>(
            pt2, M_, w_fc2_l, D_, X, D_, b_fc2_l, M_, pmeanp2);

        // lsrc #2
        gate_k<<<B_, 256>>>(pmeanp2, w1_l, w2_l, pgate);
        if (l + 1 < 2)
            scale_ln_k<<<ROWS, 256>>>(X, pgate, ln1_g + (l+1) * D_, ln1_b + (l+1) * D_, ph);
        else
            scale_k<<<(B_*N_*D_)/1024, 256>>>((float4*)X, pgate);
    }
}

// round 11
// speedup vs baseline: 1.2192x; 1.0283x over previous
#include <cuda_runtime.h>
#include <math.h>
#include <stdint.h>

#define B_  8
#define N_  1024
#define D_  256
#define H_  4
#define DH_ 64
#define M_  512
#define EPS_ 1e-5f

// ---------------- scratch (device globals; no allocations allowed) ----------
__device__ float g_h[B_*N_*D_];                 // LN output
__device__ float g_qkv[B_*N_*3*D_];             // qkv
__device__ float g_o[B_*N_*D_];                 // attn out
__device__ float g_t1[B_*N_*M_];                // fc1/gelu out
__device__ float g_t2[B_*N_*M_];                // conv/bn/gelu out
__device__ float g_meanp2[128*256];             // colsum partials per row-tile
__device__ float g_gate[B_*D_];

__device__ __forceinline__ float gelu_exact(float v) {
    return 0.5f * v * (1.f + erff(v * 0.70710678118654752f));
}

__device__ __forceinline__ void mma_tf32(float& c0, float& c1, float& c2, float& c3,
                                         float a0, float a1, float a2, float a3,
                                         float b0, float b1)
{
    asm volatile(
        "mma.sync.aligned.m16n8k8.row.col.f32.tf32.tf32.f32 "
        "{%0,%1,%2,%3},{%4,%5,%6,%7},{%8,%9},{%0,%1,%2,%3};"
        : "+f"(c0), "+f"(c1), "+f"(c2), "+f"(c3)
        : "r"(__float_as_uint(a0)), "r"(__float_as_uint(a1)),
          "r"(__float_as_uint(a2)), "r"(__float_as_uint(a3)),
          "r"(__float_as_uint(b0)), "r"(__float_as_uint(b1)));
}

__device__ __forceinline__ void cp16(uint32_t dst, const void* src) {
    asm volatile("cp.async.cg.shared.global [%0], [%1], 16;" :: "r"(dst), "l"(src));
}
__device__ __forceinline__ void cp_commit() {
    asm volatile("cp.async.commit_group;" ::: "memory");
}
template<int N>
__device__ __forceinline__ void cp_wait() {
    asm volatile("cp.async.wait_group %0;" :: "n"(N) : "memory");
}
__device__ __forceinline__ uint32_t smem_u32(const void* p) {
    return (uint32_t)__cvta_generic_to_shared(p);
}

// ---------------- flash attention (split K/V waits) --------------------------
#define FBM 64
#define FBN 64

struct FlashSmem {
    float Q[FBM][68];
    float K[2][FBN][68];
    float V[2][FBN][72];
    float P[4][16][68];
};
#define FLASH_SMEM_BYTES ((int)sizeof(FlashSmem))

__global__ __launch_bounds__(128)
void flash_k(const float* __restrict__ qkv, float* __restrict__ Og)
{
    extern __shared__ float smem_raw[];
    FlashSmem& S = *(FlashSmem*)smem_raw;

    const int bh = blockIdx.z;
    const int b = bh >> 2, h = bh & 3;
    const int m0 = blockIdx.y * FBM;
    const int tid  = threadIdx.x;
    const int warp = tid >> 5, lane = tid & 31;
    const int gid  = lane >> 2, tig = lane & 3;

    const float* qb = qkv + ((size_t)b * N_) * (3*D_) + h * DH_;

    #pragma unroll
    for (int i = 0; i < 8; i++) {
        int v = tid + i * 128;
        int r = v >> 4, dq = v & 15;
        float4 t = *(const float4*)&qb[(size_t)(m0 + r) * (3*D_) + dq * 4];
        t.x *= 0.125f; t.y *= 0.125f; t.z *= 0.125f; t.w *= 0.125f;
        *(float4*)&S.Q[r][dq * 4] = t;
    }

    auto issueK = [&](int buf, int t) {
        const float* kb = qkv + ((size_t)b * N_ + t * FBN) * (3*D_) + D_ + h * DH_;
        #pragma unroll
        for (int i = 0; i < 8; i++) {
            int v = tid + i * 128;
            int r = v >> 4, dq = v & 15;
            cp16(smem_u32(&S.K[buf][r][dq * 4]), &kb[(size_t)r * (3*D_) + dq * 4]);
        }
    };
    auto issueV = [&](int buf, int t) {
        const float* vb = qkv + ((size_t)b * N_ + t * FBN) * (3*D_) + 2*D_ + h * DH_;
        #pragma unroll
        for (int i = 0; i < 8; i++) {
            int v = tid + i * 128;
            int r = v >> 4, dq = v & 15;
            cp16(smem_u32(&S.V[buf][r][dq * 4]), &vb[(size_t)r * (3*D_) + dq * 4]);
        }
    };

    float mr0 = -1e30f, mr1 = -1e30f, l0 = 0.f, l1 = 0.f;
    float o[8][4];
    #pragma unroll
    for (int nt = 0; nt < 8; nt++)
        #pragma unroll
        for (int c = 0; c < 4; c++) o[nt][c] = 0.f;

    const int qrow = warp * 16 + gid;
    const int NTiles = N_ / FBN;

    issueK(0, 0); cp_commit();
    issueV(0, 0); cp_commit();
    for (int t = 0; t < NTiles; t++) {
        int cur = t & 1;
        cp_wait<1>();
        __syncthreads();
        if (t + 1 < NTiles) issueK(cur ^ 1, t + 1);
        cp_commit();

        float s[8][4];
        #pragma unroll
        for (int nt = 0; nt < 8; nt++)
            #pragma unroll
            for (int c = 0; c < 4; c++) s[nt][c] = 0.f;

        #pragma unroll
        for (int ks = 0; ks < DH_; ks += 8) {
            float a0 = S.Q[qrow    ][ks + tig];
            float a1 = S.Q[qrow + 8][ks + tig];
            float a2 = S.Q[qrow    ][ks + tig + 4];
            float a3 = S.Q[qrow + 8][ks + tig + 4];
            #pragma unroll
            for (int nt = 0; nt < 8; nt++) {
                float b0 = S.K[cur][nt * 8 + gid][ks + tig];
                float b1 = S.K[cur][nt * 8 + gid][ks + tig + 4];
                mma_tf32(s[nt][0], s[nt][1], s[nt][2], s[nt][3],
                         a0, a1, a2, a3, b0, b1);
            }
        }

        float rm0 = -1e30f, rm1 = -1e30f;
        #pragma unroll
        for (int nt = 0; nt < 8; nt++) {
            rm0 = fmaxf(rm0, fmaxf(s[nt][0], s[nt][1]));
            rm1 = fmaxf(rm1, fmaxf(s[nt][2], s[nt][3]));
        }
        rm0 = fmaxf(rm0, __shfl_xor_sync(0xffffffff, rm0, 1));
        rm0 = fmaxf(rm0, __shfl_xor_sync(0xffffffff, rm0, 2));
        rm1 = fmaxf(rm1, __shfl_xor_sync(0xffffffff, rm1, 1));
        rm1 = fmaxf(rm1, __shfl_xor_sync(0xffffffff, rm1, 2));

        float mn0 = fmaxf(mr0, rm0), mn1 = fmaxf(mr1, rm1);
        float sc0 = __expf(mr0 - mn0), sc1 = __expf(mr1 - mn1);
        mr0 = mn0; mr1 = mn1;

        float rs0 = 0.f, rs1 = 0.f;
        #pragma unroll
        for (int nt = 0; nt < 8; nt++) {
            s[nt][0] = __expf(s[nt][0] - mn0);
            s[nt][1] = __expf(s[nt][1] - mn0);
            s[nt][2] = __expf(s[nt][2] - mn1);
            s[nt][3] = __expf(s[nt][3] - mn1);
            rs0 += s[nt][0] + s[nt][1];
            rs1 += s[nt][2] + s[nt][3];
        }
        rs0 += __shfl_xor_sync(0xffffffff, rs0, 1);
        rs0 += __shfl_xor_sync(0xffffffff, rs0, 2);
        rs1 += __shfl_xor_sync(0xffffffff, rs1, 1);
        rs1 += __shfl_xor_sync(0xffffffff, rs1, 2);
        l0 = l0 * sc0 + rs0;
        l1 = l1 * sc1 + rs1;

        #pragma unroll
        for (int nt = 0; nt < 8; nt++) {
            o[nt][0] *= sc0; o[nt][1] *= sc0;
            o[nt][2] *= sc1; o[nt][3] *= sc1;
        }

        cp_wait<1>();
        __syncthreads();
        if (t + 1 < NTiles) issueV(cur ^ 1, t + 1);
        cp_commit();

        #pragma unroll
        for (int nt = 0; nt < 8; nt++) {
            S.P[warp][gid    ][nt * 8 + tig * 2    ] = s[nt][0];
            S.P[warp][gid    ][nt * 8 + tig * 2 + 1] = s[nt][1];
            S.P[warp][gid + 8][nt * 8 + tig * 2    ] = s[nt][2];
            S.P[warp][gid + 8][nt * 8 + tig * 2 + 1] = s[nt][3];
        }
        __syncwarp();

        #pragma unroll
        for (int ks = 0; ks < FBN; ks += 8) {
            float a0 = S.P[warp][gid    ][ks + tig];
            float a1 = S.P[warp][gid + 8][ks + tig];
            float a2 = S.P[warp][gid    ][ks + tig + 4];
            float a3 = S.P[warp][gid + 8][ks + tig + 4];
            #pragma unroll
            for (int nt = 0; nt < 8; nt++) {
                float b0 = S.V[cur][ks + tig    ][nt * 8 + gid];
                float b1 = S.V[cur][ks + tig + 4][nt * 8 + gid];
                mma_tf32(o[nt][0], o[nt][1], o[nt][2], o[nt][3],
                         a0, a1, a2, a3, b0, b1);
            }
        }
        __syncwarp();
    }

    float inv0 = 1.f / l0, inv1 = 1.f / l1;
    int r0 = m0 + qrow;
    float* ob0 = Og + ((size_t)b * N_ + r0    ) * D_ + h * DH_;
    float* ob1 = Og + ((size_t)b * N_ + r0 + 8) * D_ + h * DH_;
    #pragma unroll
    for (int nt = 0; nt < 8; nt++) {
        int col = nt * 8 + tig * 2;
        *(float2*)&ob0[col] = make_float2(o[nt][0] * inv0, o[nt][1] * inv0);
        *(float2*)&ob1[col] = make_float2(o[nt][2] * inv1, o[nt][3] * inv1);
    }
}

// ---------------- big dense GEMM (tf32, multi-stage; gemm7 lineage) ----------
template<int BM, int BN, int BK, int WSM, int WSN, int ACT, int STAGES>
__global__ __launch_bounds__(WSM*WSN*32)
void gemm7_k(const float* __restrict__ A, int lda,
             const float* __restrict__ Bm, int ldb,
             float* __restrict__ C, int ldc,
             const float* __restrict__ bias, int K)
{
    constexpr int NT = WSM * WSN * 32;
    constexpr int WM = BM / WSM, WN = BN / WSN;
    constexpr int MT = WM / 16, NTL = WN / 8;
    constexpr int SA = BK + 4;
    constexpr int SB = BN + 8;
    constexpr int LA = BM * BK / (4 * NT);
    constexpr int LB = BN * BK / (4 * NT);
    constexpr int KQ = BK / 4;

    extern __shared__ float smem[];
    float (*As)[BM][SA] = reinterpret_cast<float(*)[BM][SA]>(smem);
    float (*Bs)[BK][SB] = reinterpret_cast<float(*)[BK][SB]>(smem + STAGES * BM * SA);

    const int m0 = blockIdx.y * BM;
    const int n0 = blockIdx.x * BN;
    const int tid   = threadIdx.x;
    const int warp  = tid >> 5;
    const int lane  = tid & 31;
    const int gid   = lane >> 2;
    const int tig   = lane & 3;
    const int warpM = warp / WSN;
    const int warpN = warp % WSN;

    auto issue = [&](int buf, int k0) {
        #pragma unroll
        for (int i = 0; i < LA; i++) {
            int v = tid + i * NT;
            int m = v / KQ, kq = v % KQ;
            cp16(smem_u32(&As[buf][m][kq * 4]),
                 &A[(size_t)(m0 + m) * lda + k0 + kq * 4]);
        }
        #pragma unroll
        for (int i = 0; i < LB; i++) {
            int v = tid + i * NT;
            int nq = v % (BN / 4), k = v / (BN / 4);
            cp16(smem_u32(&Bs[buf][k][nq * 4]),
                 &Bm[(size_t)(k0 + k) * ldb + n0 + nq * 4]);
        }
    };

    float acc[MT][NTL][4];
    #pragma unroll
    for (int i = 0; i < MT; i++)
        #pragma unroll
        for (int j = 0; j < NTL; j++)
            #pragma unroll
            for (int c = 0; c < 4; c++) acc[i][j][c] = 0.f;

    const int NI = K / BK;
    #pragma unroll
    for (int s = 0; s < STAGES - 1; s++) { issue(s, s * BK); cp_commit(); }

    int cur = 0;
    for (int i = 0; i < NI; i++) {
        cp_wait<STAGES - 2>();
        __syncthreads();
        int nx = i + STAGES - 1;
        if (nx < NI) issue(nx % STAGES, nx * BK);
        cp_commit();

        #pragma unroll
        for (int ks = 0; ks < BK; ks += 8) {
            float af[MT][4], bf[NTL][2];
            #pragma unroll
            for (int mt = 0; mt < MT; mt++) {
                int rb0 = warpM * WM + mt * 16;
                af[mt][0] = As[cur][rb0 + gid    ][ks + tig];
                af[mt][1] = As[cur][rb0 + gid + 8][ks + tig];
                af[mt][2] = As[cur][rb0 + gid    ][ks + tig + 4];
                af[mt][3] = As[cur][rb0 + gid + 8][ks + tig + 4];
            }
            #pragma unroll
            for (int nt = 0; nt < NTL; nt++) {
                int cb0 = warpN * WN + nt * 8;
                bf[nt][0] = Bs[cur][ks + tig    ][cb0 + gid];
                bf[nt][1] = Bs[cur][ks + tig + 4][cb0 + gid];
            }
            #pragma unroll
            for (int mt = 0; mt < MT; mt++)
                #pragma unroll
                for (int nt = 0; nt < NTL; nt++)
                    mma_tf32(acc[mt][nt][0], acc[mt][nt][1],
                             acc[mt][nt][2], acc[mt][nt][3],
                             af[mt][0], af[mt][1], af[mt][2], af[mt][3],
                             bf[nt][0], bf[nt][1]);
        }
        cur++; if (cur == STAGES) cur = 0;
    }

    #pragma unroll
    for (int mt = 0; mt < MT; mt++) {
        int row = m0 + warpM * WM + mt * 16 + gid;
        #pragma unroll
        for (int nt = 0; nt < NTL; nt++) {
            int col = n0 + warpN * WN + nt * 8 + tig * 2;
            float v0 = acc[mt][nt][0];
            float v1 = acc[mt][nt][1];
            float v2 = acc[mt][nt][2];
            float v3 = acc[mt][nt][3];
            if (bias) {
                float b0v = bias[col], b1v = bias[col + 1];
                v0 += b0v; v1 += b1v; v2 += b0v; v3 += b1v;
            }
            if (ACT == 1) {
                v0 = gelu_exact(v0); v1 = gelu_exact(v1);
                v2 = gelu_exact(v2); v3 = gelu_exact(v3);
            }
            *(float2*)&C[(size_t)row * ldc + col]       = make_float2(v0, v1);
            *(float2*)&C[(size_t)(row + 8) * ldc + col] = make_float2(v2, v3);
        }
    }
}

constexpr int gemm7_smem(int BM, int BN, int BK, int S) {
    return (S * BM * (BK + 4) + S * BK * (BN + 8)) * 4;
}

// ---------------- thin GEMM: 64x64, BK=32, C-tile prefetch + staged epilogue -
// X(tile) += A @ B + bias, and column partials of the result tile.
#define TSTG 3
constexpr int thin_smem() {
    return (TSTG * 64 * 36 + TSTG * 32 * 72 + 64 * 68) * 4;   // 72704
}

__global__ __launch_bounds__(128)
void gemm_thin_k(const float* __restrict__ A, int lda,
                 const float* __restrict__ Bm, int ldb,
                 float* __restrict__ C, int ldc,
                 const float* __restrict__ bias, int K,
                 float* __restrict__ meanp2)
{
    constexpr int BM = 64, BN = 64, BK = 32;
    constexpr int MT = 2, NTL = 4;              // 2x2 warps, 32x32 warp tile
    constexpr int SA = 36, SB = 72;

    extern __shared__ float smem[];
    float (*As)[BM][SA] = reinterpret_cast<float(*)[BM][SA]>(smem);
    float (*Bs)[BK][SB] = reinterpret_cast<float(*)[BK][SB]>(smem + TSTG * BM * SA);
    float (*Cs)[68]     = reinterpret_cast<float(*)[68]>(smem + TSTG * BM * SA + TSTG * BK * SB);
    __shared__ float scred[4][64];

    const int m0 = blockIdx.y * BM;
    const int n0 = blockIdx.x * BN;
    const int tid   = threadIdx.x;
    const int warp  = tid >> 5;
    const int lane  = tid & 31;
    const int gid   = lane >> 2;
    const int tig   = lane & 3;
    const int warpM = warp >> 1;
    const int warpN = warp & 1;

    // prefetch C tile (residual) — first commit group, completes during mainloop
    #pragma unroll
    for (int i = 0; i < 8; i++) {
        int v = tid + i * 128;
        int r = v >> 4, c4 = v & 15;
        cp16(smem_u32(&Cs[r][c4 * 4]), &C[(size_t)(m0 + r) * ldc + n0 + c4 * 4]);
    }
    cp_commit();

    auto issue = [&](int buf, int k0) {
        #pragma unroll
        for (int i = 0; i < 4; i++) {
            int v = tid + i * 128;
            int m = v >> 3, kq = v & 7;
            cp16(smem_u32(&As[buf][m][kq * 4]),
                 &A[(size_t)(m0 + m) * lda + k0 + kq * 4]);
        }
        #pragma unroll
        for (int i = 0; i < 4; i++) {
            int v = tid + i * 128;
            int nq = v & 15, k = v >> 4;
            cp16(smem_u32(&Bs[buf][k][nq * 4]),
                 &Bm[(size_t)(k0 + k) * ldb + n0 + nq * 4]);
        }
    };

    float acc[MT][NTL][4];
    #pragma unroll
    for (int i = 0; i < MT; i++)
        #pragma unroll
        for (int j = 0; j < NTL; j++)
            #pragma unroll
            for (int c = 0; c < 4; c++) acc[i][j][c] = 0.f;

    const int NI = K / BK;
    #pragma unroll
    for (int s = 0; s < TSTG - 1; s++) { issue(s, s * BK); cp_commit(); }

    int cur = 0;
    for (int i = 0; i < NI; i++) {
        cp_wait<TSTG - 2>();
        __syncthreads();
        int nx = i + TSTG - 1;
        if (nx < NI) issue(nx % TSTG, nx * BK);
        cp_commit();

        #pragma unroll
        for (int ks = 0; ks < BK; ks += 8) {
            float af[MT][4], bf[NTL][2];
            #pragma unroll
            for (int mt = 0; mt < MT; mt++) {
                int rb0 = warpM * 32 + mt * 16;
                af[mt][0] = As[cur][rb0 + gid    ][ks + tig];
                af[mt][1] = As[cur][rb0 + gid + 8][ks + tig];
                af[mt][2] = As[cur][rb0 + gid    ][ks + tig + 4];
                af[mt][3] = As[cur][rb0 + gid + 8][ks + tig + 4];
            }
            #pragma unroll
            for (int nt = 0; nt < NTL; nt++) {
                int cb0 = warpN * 32 + nt * 8;
                bf[nt][0] = Bs[cur][ks + tig    ][cb0 + gid];
                bf[nt][1] = Bs[cur][ks + tig + 4][cb0 + gid];
            }
            #pragma unroll
            for (int mt = 0; mt < MT; mt++)
                #pragma unroll
                for (int nt = 0; nt < NTL; nt++)
                    mma_tf32(acc[mt][nt][0], acc[mt][nt][1],
                             acc[mt][nt][2], acc[mt][nt][3],
                             af[mt][0], af[mt][1], af[mt][2], af[mt][3],
                             bf[nt][0], bf[nt][1]);
        }
        cur++; if (cur == TSTG) cur = 0;
    }

    // stage acc + bias + residual into Cs
    #pragma unroll
    for (int mt = 0; mt < MT; mt++) {
        int lr = warpM * 32 + mt * 16 + gid;
        #pragma unroll
        for (int nt = 0; nt < NTL; nt++) {
            int lc = warpN * 32 + nt * 8 + tig * 2;
            float b0v = bias[n0 + lc], b1v = bias[n0 + lc + 1];
            float2 c0 = *(float2*)&Cs[lr][lc];
            float2 c1 = *(float2*)&Cs[lr + 8][lc];
            *(float2*)&Cs[lr][lc] =
                make_float2(acc[mt][nt][0] + b0v + c0.x, acc[mt][nt][1] + b1v + c0.y);
            *(float2*)&Cs[lr + 8][lc] =
                make_float2(acc[mt][nt][2] + b0v + c1.x, acc[mt][nt][3] + b1v + c1.y);
        }
    }
    __syncthreads();

    // coalesced float4 writeback + column partial sums
    int c4 = tid & 15, rg = tid >> 4;
    float cs0 = 0.f, cs1 = 0.f, cs2 = 0.f, cs3 = 0.f;
    #pragma unroll
    for (int i = 0; i < 8; i++) {
        int r = rg + i * 8;
        float4 t = *(float4*)&Cs[r][c4 * 4];
        cs0 += t.x; cs1 += t.y; cs2 += t.z; cs3 += t.w;
        *(float4*)&C[(size_t)(m0 + r) * ldc + n0 + c4 * 4] = t;
    }
    cs0 += __shfl_xor_sync(0xffffffff, cs0, 16);
    cs1 += __shfl_xor_sync(0xffffffff, cs1, 16);
    cs2 += __shfl_xor_sync(0xffffffff, cs2, 16);
    cs3 += __shfl_xor_sync(0xffffffff, cs3, 16);
    if (lane < 16)
        *(float4*)&scred[warp][lane * 4] = make_float4(cs0, cs1, cs2, cs3);
    __syncthreads();
    if (tid < 64) {
        float s = scred[0][tid] + scred[1][tid] + scred[2][tid] + scred[3][tid];
        meanp2[(size_t)blockIdx.y * 256 + n0 + tid] = s;
    }
}

// ---------------- fused copy + layernorm (float4, 4 rows/CTA) ----------------
__global__ void copy_ln_k(const float4* __restrict__ xin, float4* __restrict__ X,
                          const float* __restrict__ g, const float* __restrict__ b,
                          float4* __restrict__ out)
{
    int tid = threadIdx.x;
    int rib = tid >> 6, t64 = tid & 63;
    int row = blockIdx.x * 4 + rib;
    int idx = row * 64 + t64;
    int lane = tid & 31, wir = (tid >> 5) & 1;
    __shared__ float r1[4][2], r2[4][2];

    float4 v = xin[idx];
    X[idx] = v;
    float s  = v.x + v.y + v.z + v.w;
    float s2 = v.x*v.x + v.y*v.y + v.z*v.z + v.w*v.w;
    #pragma unroll
    for (int m = 16; m > 0; m >>= 1) {
        s  += __shfl_xor_sync(0xffffffff, s, m);
        s2 += __shfl_xor_sync(0xffffffff, s2, m);
    }
    if (lane == 0) { r1[rib][wir] = s; r2[rib][wir] = s2; }
    __syncthreads();
    float ts = r1[rib][0] + r1[rib][1], ts2 = r2[rib][0] + r2[rib][1];
    float mu = ts * (1.f / D_);
    float var = ts2 * (1.f / D_) - mu * mu;
    float rs = rsqrtf(var + EPS_);
    float4 gg = *(const float4*)&g[t64 * 4];
    float4 bb = *(const float4*)&b[t64 * 4];
    float4 o;
    o.x = (v.x - mu) * rs * gg.x + bb.x;
    o.y = (v.y - mu) * rs * gg.y + bb.y;
    o.z = (v.z - mu) * rs * gg.z + bb.z;
    o.w = (v.w - mu) * rs * gg.w + bb.w;
    out[idx] = o;
}

// ---------------- fused scale + layernorm (float4, 4 rows/CTA) ---------------
__global__ void scale_ln_k(float4* __restrict__ X, const float* __restrict__ gate,
                           const float* __restrict__ g, const float* __restrict__ b,
                           float4* __restrict__ out)
{
    int tid = threadIdx.x;
    int rib = tid >> 6, t64 = tid & 63;
    int row = blockIdx.x * 4 + rib;
    int bbatch = row >> 10;
    int idx = row * 64 + t64;
    int lane = tid & 31, wir = (tid >> 5) & 1;
    __shared__ float r1[4][2], r2[4][2];

    float4 gv = *(const float4*)&gate[bbatch * D_ + t64 * 4];
    float4 v = X[idx];
    v.x *= gv.x; v.y *= gv.y; v.z *= gv.z; v.w *= gv.w;
    X[idx] = v;
    float s  = v.x + v.y + v.z + v.w;
    float s2 = v.x*v.x + v.y*v.y + v.z*v.z + v.w*v.w;
    #pragma unroll
    for (int m = 16; m > 0; m >>= 1) {
        s  += __shfl_xor_sync(0xffffffff, s, m);
        s2 += __shfl_xor_sync(0xffffffff, s2, m);
    }
    if (lane == 0) { r1[rib][wir] = s; r2[rib][wir] = s2; }
    __syncthreads();
    float ts = r1[rib][0] + r1[rib][1], ts2 = r2[rib][0] + r2[rib][1];
    float mu = ts * (1.f / D_);
    float var = ts2 * (1.f / D_) - mu * mu;
    float rs = rsqrtf(var + EPS_);
    float4 gg = *(const float4*)&g[t64 * 4];
    float4 bb = *(const float4*)&b[t64 * 4];
    float4 o;
    o.x = (v.x - mu) * rs * gg.x + bb.x;
    o.y = (v.y - mu) * rs * gg.y + bb.y;
    o.z = (v.z - mu) * rs * gg.z + bb.z;
    o.w = (v.w - mu) * rs * gg.w + bb.w;
    out[idx] = o;
}

// SE gate: s = sigmoid(relu(mean @ w1) @ w2); one block per batch
__global__ void gate_k(const float* __restrict__ meanp2, const float* __restrict__ w1,
                       const float* __restrict__ w2, float* __restrict__ gatebuf)
{
    int b = blockIdx.x, tid = threadIdx.x;
    __shared__ float m[D_];
    __shared__ float t[D_ / 4];
    float acc0 = 0.f;
    #pragma unroll
    for (int i = 0; i < 16; i++)
        acc0 += meanp2[((size_t)(b * 16 + i)) * 256 + tid];
    m[tid] = acc0 * (1.f / N_);
    __syncthreads();
    if (tid < D_ / 4) {
        float acc = 0.f;
        #pragma unroll 8
        for (int d = 0; d < D_; d++) acc += m[d] * w1[d * (D_ / 4) + tid];
        t[tid] = fmaxf(acc, 0.f);
    }
    __syncthreads();
    float acc = 0.f;
    #pragma unroll 8
    for (int j = 0; j < D_ / 4; j++) acc += t[j] * w2[j * D_ + tid];
    gatebuf[b * D_ + tid] = 1.f / (1.f + expf(-acc));
}

__global__ void scale_k(float4* __restrict__ x, const float* __restrict__ gate)
{
    int idx = blockIdx.x * 256 + threadIdx.x;      // float4 index
    int d4 = idx & (D_ / 4 - 1);
    int b = idx / (N_ * D_ / 4);
    const float4 gv = *(const float4*)&gate[b * D_ + d4 * 4];
    float4 v = x[idx];
    v.x *= gv.x; v.y *= gv.y; v.z *= gv.z; v.w *= gv.w;
    x[idx] = v;
}

// depthwise 1x3 conv + center-tap + BN(eval) + exact gelu (float4)
__global__ void conv_k(const float4* __restrict__ y, const float* __restrict__ wh,
                       const float* __restrict__ bh, const float* __restrict__ wv,
                       const float* __restrict__ bv, const float* __restrict__ bng,
                       const float* __restrict__ bnb, const float* __restrict__ bnm,
                       const float* __restrict__ bnv, float4* __restrict__ out)
{
    int idx = blockIdx.x * 256 + threadIdx.x;      // float4 index
    int m4 = idx & (M_ / 4 - 1);
    int n = (idx / (M_ / 4)) & (N_ - 1);
    int m = m4 * 4;
    float4 y0 = y[idx];
    float4 ym = (n > 0)      ? y[idx - M_ / 4] : make_float4(0.f, 0.f, 0.f, 0.f);
    float4 yp = (n < N_ - 1) ? y[idx + M_ / 4] : make_float4(0.f, 0.f, 0.f, 0.f);
    float r[4];
    float y0a[4] = {y0.x, y0.y, y0.z, y0.w};
    float yma[4] = {ym.x, ym.y, ym.z, ym.w};
    float ypa[4] = {yp.x, yp.y, yp.z, yp.w};
    #pragma unroll
    for (int j = 0; j < 4; j++) {
        int mm = m + j;
        float ch = wh[mm * 3 + 0] * yma[j] + wh[mm * 3 + 1] * y0a[j]
                 + wh[mm * 3 + 2] * ypa[j] + bh[mm];
        float cv = wv[mm * 3 + 1] * y0a[j] + bv[mm];
        float zz = ch + cv;
        zz = (zz - bnm[mm]) * rsqrtf(bnv[mm] + EPS_) * bng[mm] + bnb[mm];
        r[j] = gelu_exact(zz);
    }
    out[idx] = make_float4(r[0], r[1], r[2], r[3]);
}

// ---------------- driver -----------------------------------------------------
extern "C" void kernel_launch(void* const* d_in, const int* in_sizes, int n_in,
                              void* d_out, int out_size)
{
    const float* x_in  = (const float*)d_in[0];
    const float* ln1_g = (const float*)d_in[1];
    const float* ln1_b = (const float*)d_in[2];
    const float* w_qkv = (const float*)d_in[3];
    const float* w_out = (const float*)d_in[4];
    const float* b_out = (const float*)d_in[5];
    const float* ln2_g = (const float*)d_in[6];
    const float* ln2_b = (const float*)d_in[7];
    const float* w_fc1 = (const float*)d_in[8];
    const float* b_fc1 = (const float*)d_in[9];
    const float* wh    = (const float*)d_in[10];
    const float* bh    = (const float*)d_in[11];
    const float* wv    = (const float*)d_in[12];
    const float* bv    = (const float*)d_in[13];
    const float* bn_g  = (const float*)d_in[14];
    const float* bn_b  = (const float*)d_in[15];
    const float* bn_m  = (const float*)d_in[16];
    const float* bn_v  = (const float*)d_in[17];
    const float* w_fc2 = (const float*)d_in[18];
    const float* b_fc2 = (const float*)d_in[19];
    const float* ls_w1 = (const float*)d_in[20];
    const float* ls_w2 = (const float*)d_in[21];

    float *ph, *pqkv, *po, *pt1, *pt2, *pmeanp2, *pgate;
    cudaGetSymbolAddress((void**)&ph,      g_h);
    cudaGetSymbolAddress((void**)&pqkv,    g_qkv);
    cudaGetSymbolAddress((void**)&po,      g_o);
    cudaGetSymbolAddress((void**)&pt1,     g_t1);
    cudaGetSymbolAddress((void**)&pt2,     g_t2);
    cudaGetSymbolAddress((void**)&pmeanp2, g_meanp2);
    cudaGetSymbolAddress((void**)&pgate,   g_gate);

    constexpr int SM_BIG  = gemm7_smem(128, 128, 16, 3);   // 56832
    constexpr int SM_THIN = thin_smem();                   // 72704

    cudaFuncSetAttribute(flash_k, cudaFuncAttributeMaxDynamicSharedMemorySize,
                         FLASH_SMEM_BYTES);
    cudaFuncSetAttribute(gemm7_k<128,128,16,2,4,0,3>,
                         cudaFuncAttributeMaxDynamicSharedMemorySize, SM_BIG);
    cudaFuncSetAttribute(gemm7_k<128,128,16,2,4,1,3>,
                         cudaFuncAttributeMaxDynamicSharedMemorySize, SM_BIG);
    cudaFuncSetAttribute(gemm_thin_k,
                         cudaFuncAttributeMaxDynamicSharedMemorySize, SM_THIN);

    float* X = (float*)d_out;
    const int ROWS = B_ * N_;   // 8192

    for (int l = 0; l < 2; l++) {
        const float* w_qkv_l = w_qkv + (size_t)l * D_ * 3 * D_;
        const float* w_out_l = w_out + (size_t)l * D_ * D_;
        const float* b_out_l = b_out + (size_t)l * D_;
        const float* w_fc1_l = w_fc1 + (size_t)l * D_ * M_;
        const float* b_fc1_l = b_fc1 + (size_t)l * M_;
        const float* w_fc2_l = w_fc2 + (size_t)l * M_ * D_;
        const float* b_fc2_l = b_fc2 + (size_t)l * D_;
        const float* w1_l    = ls_w1 + (size_t)l * D_ * (D_/4);
        const float* w2_l    = ls_w2 + (size_t)l * (D_/4) * D_;

        // --- MHSA ---  (h = LN1(X); layer 0 fuses the initial copy)
        if (l == 0)
            copy_ln_k<<<ROWS/4, 256>>>((const float4*)x_in, (float4*)X,
                                       ln1_g, ln1_b, (float4*)ph);

        // qkv = h @ w_qkv
        gemm7_k<128,128,16,2,4,0,3><<<dim3((3*D_)/128, ROWS/128, 1), 256, SM_BIG>>>(
            ph, D_, w_qkv_l, 3*D_, pqkv, 3*D_, nullptr, D_);

        // fused attention
        flash_k<<<dim3(1, N_/FBM, B_*H_), 128, FLASH_SMEM_BYTES>>>(pqkv, po);

        // X += o @ w_out + b_out  (residual + colsum fused, prefetched C)
        gemm_thin_k<<<dim3(D_/64, ROWS/64, 1), 128, SM_THIN>>>(
            po, D_, w_out_l, D_, X, D_, b_out_l, D_, pmeanp2);

        // lsrc #1
        gate_k<<<B_, 256>>>(pmeanp2, w1_l, w2_l, pgate);
        scale_ln_k<<<ROWS/4, 256>>>((float4*)X, pgate,
                                    ln2_g + l * D_, ln2_b + l * D_, (float4*)ph);

        // --- MLP ---
        gemm7_k<128,128,16,2,4,1,3><<<dim3(M_/128, ROWS/128, 1), 256, SM_BIG>>>(
            ph, D_, w_fc1_l, M_, pt1, M_, b_fc1_l, D_);

        conv_k<<<(B_*N_*M_)/1024, 256>>>(
            (const float4*)pt1, wh + (size_t)l*M_*3, bh + (size_t)l*M_,
            wv + (size_t)l*M_*3, bv + (size_t)l*M_,
            bn_g + (size_t)l*M_, bn_b + (size_t)l*M_,
            bn_m + (size_t)l*M_, bn_v + (size_t)l*M_, (float4*)pt2);

        // X += t2 @ w_fc2 + b_fc2
        gemm_thin_k<<<dim3(D_/64, ROWS/64, 1), 128, SM_THIN>>>(
            pt2, M_, w_fc2_l, D_, X, D_, b_fc2_l, M_, pmeanp2);

        // lsrc #2
        gate_k<<<B_, 256>>>(pmeanp2, w1_l, w2_l, pgate);
        if (l + 1 < 2)
            scale_ln_k<<<ROWS/4, 256>>>((float4*)X, pgate,
                                        ln1_g + (l+1) * D_, ln1_b + (l+1) * D_,
                                        (float4*)ph);
        else
            scale_k<<<(B_*N_*D_)/1024, 256>>>((float4*)X, pgate);
    }
}